// round 1
// baseline (speedup 1.0000x reference)
#include <cuda_runtime.h>
#include <cuda_bf16.h>
#include <math.h>

// ---------------- problem constants ----------------
#define BSZ     2
#define SEQL    2048
#define NTOK    (BSZ*SEQL)        // 4096
#define DMODEL  512
#define DINNER  1024
#define NH      16
#define HD      64
#define DSTATE  64
#define DCONV   4
#define CONVDIM 1152              // DINNER + 2*DSTATE
#define DINPROJ 2192              // 2*DINNER + 2*DSTATE + NH
#define NLAYERS 12
#define CHUNKL  128
#define NCH     16                // chunks per batch
#define NBC     (BSZ*NCH)         // 32
#define KOUT    30                // KLEN*3

// ---------------- scratch (static device globals; allocation-free) ----------
__device__ float g_h   [NTOK*DMODEL];
__device__ float g_xn  [NTOK*DMODEL];
__device__ float g_zx  [NTOK*DINPROJ];
__device__ float g_xc  [NTOK*CONVDIM];
__device__ float g_dtv [NTOK*NH];
__device__ float g_acum[NTOK*NH];
__device__ float g_dec [NBC*NH];
__device__ float g_sc  [NBC*CHUNKL*CHUNKL];
__device__ float g_y   [NTOK*DINNER];
__device__ float g_S   [NBC*NH*HD*DSTATE];
__device__ float g_hs  [NBC*NH*HD*DSTATE];
__device__ float g_yg  [NTOK*DINNER];

// ---------------- helpers ----------------
__device__ __forceinline__ float softplusf(float x){
    return (x > 20.f) ? x : log1pf(expf(x));
}
__device__ __forceinline__ float siluf(float x){
    return x / (1.f + expf(-x));
}
__device__ __forceinline__ float blockReduceSum(float v){
    __shared__ float sh[32];
    #pragma unroll
    for (int o = 16; o; o >>= 1) v += __shfl_xor_sync(0xffffffffu, v, o);
    int w = threadIdx.x >> 5;
    if ((threadIdx.x & 31) == 0) sh[w] = v;
    __syncthreads();
    int nw = blockDim.x >> 5;
    float r = (threadIdx.x < nw) ? sh[threadIdx.x] : 0.f;
    if (w == 0){
        #pragma unroll
        for (int o = 16; o; o >>= 1) r += __shfl_xor_sync(0xffffffffu, r, o);
        if (threadIdx.x == 0) sh[0] = r;
    }
    __syncthreads();
    return sh[0];
}

// ---------------- embedding: x@W_embed + nerf_pe ----------------
__global__ void k_embed(const float* __restrict__ x, const float* __restrict__ W){
    int idx = blockIdx.x * blockDim.x + threadIdx.x;
    if (idx >= NTOK * DMODEL) return;
    int t = idx / DMODEL, d = idx % DMODEL;
    float x0 = x[t*3+0]; if (x0 == -100.f) x0 = 0.f;
    float x1 = x[t*3+1]; if (x1 == -100.f) x1 = 0.f;
    float x2 = x[t*3+2]; if (x2 == -100.f) x2 = 0.f;
    float acc = x0 * W[0*DMODEL + d] + x1 * W[1*DMODEL + d] + x2 * W[2*DMODEL + d];
    // nerf_pe: 3 channels x (85 sin + 85 cos) = 510, padded to 512
    if (d < 510){
        int c = d / 170, r = d % 170;
        float xv = (c == 0) ? x0 : ((c == 1) ? x1 : x2);
        float pe;
        if (r < 85) pe = sinf(xv * exp2f((float)r));
        else        pe = cosf(xv * exp2f((float)(r - 85)));
        acc += pe;
    }
    g_h[idx] = acc;
}

// ---------------- rmsnorm (generic D) ----------------
__global__ void k_rmsnorm(const float* __restrict__ x, const float* __restrict__ w,
                          float* __restrict__ o, int D){
    int t = blockIdx.x;
    const float* xr = x + (size_t)t * D;
    float ss = 0.f;
    for (int d = threadIdx.x; d < D; d += blockDim.x){
        float v = xr[d];
        ss += v * v;
    }
    ss = blockReduceSum(ss);
    float rs = rsqrtf(ss / (float)D + 1e-5f);
    float* orow = o + (size_t)t * D;
    for (int d = threadIdx.x; d < D; d += blockDim.x)
        orow[d] = xr[d] * rs * w[d];
}

// ---------------- generic SGEMM: C[MxN] = A[MxK] @ B[KxN] (+ R) ----------------
// 128x128x8 tiles, 256 threads, 8x8 microtile. M must be multiple of 128, K of 8.
__global__ void k_gemm(const float* __restrict__ A, const float* __restrict__ B,
                       float* __restrict__ C, const float* __restrict__ R,
                       int M, int N, int K){
    __shared__ float As[8][128];
    __shared__ float Bs[8][128];
    int n0 = blockIdx.x * 128;
    int m0 = blockIdx.y * 128;
    int tid = threadIdx.x;
    int tx = tid & 15, ty = tid >> 4;
    int arow = tid >> 1, acol = (tid & 1) * 4;
    int brow = tid >> 5, bcol = (tid & 31) * 4;
    float acc[8][8];
    #pragma unroll
    for (int r = 0; r < 8; r++)
        #pragma unroll
        for (int c = 0; c < 8; c++) acc[r][c] = 0.f;

    for (int k0 = 0; k0 < K; k0 += 8){
        float4 av = *(const float4*)&A[(size_t)(m0 + arow) * K + k0 + acol];
        As[acol+0][arow] = av.x; As[acol+1][arow] = av.y;
        As[acol+2][arow] = av.z; As[acol+3][arow] = av.w;
        int gcol = n0 + bcol;
        float4 bv = make_float4(0.f,0.f,0.f,0.f);
        if (gcol < N) bv = *(const float4*)&B[(size_t)(k0 + brow) * N + gcol];
        *(float4*)&Bs[brow][bcol] = bv;
        __syncthreads();
        #pragma unroll
        for (int kk = 0; kk < 8; kk++){
            float a[8], b[8];
            *(float4*)&a[0] = *(const float4*)&As[kk][ty*8];
            *(float4*)&a[4] = *(const float4*)&As[kk][ty*8+4];
            *(float4*)&b[0] = *(const float4*)&Bs[kk][tx*8];
            *(float4*)&b[4] = *(const float4*)&Bs[kk][tx*8+4];
            #pragma unroll
            for (int r = 0; r < 8; r++)
                #pragma unroll
                for (int c = 0; c < 8; c++)
                    acc[r][c] += a[r] * b[c];
        }
        __syncthreads();
    }
    #pragma unroll
    for (int r = 0; r < 8; r++){
        int row = m0 + ty*8 + r;
        #pragma unroll
        for (int c = 0; c < 8; c++){
            int col = n0 + tx*8 + c;
            if (col < N){
                float v = acc[r][c];
                if (R) v += R[(size_t)row * N + col];
                C[(size_t)row * N + col] = v;
            }
        }
    }
}

// ---------------- causal depthwise conv + silu ----------------
__global__ void k_conv(const float* __restrict__ cw, const float* __restrict__ cb){
    int idx = blockIdx.x * blockDim.x + threadIdx.x;
    if (idx >= NTOK * CONVDIM) return;
    int t = idx / CONVDIM, ch = idx % CONVDIM;
    int l = t % SEQL;
    float acc = cb[ch];
    #pragma unroll
    for (int k = 0; k < DCONV; k++){
        int l2 = l + k - (DCONV - 1);
        if (l2 >= 0)
            acc += g_zx[(size_t)(t + l2 - l) * DINPROJ + DINNER + ch] * cw[ch*DCONV + k];
    }
    g_xc[idx] = siluf(acc);
}

// ---------------- dt prep: softplus, a=dt*A, inclusive cumsum per chunk ----------
__global__ void k_dt(const float* __restrict__ dtb, const float* __restrict__ Alog){
    int bc = blockIdx.x >> 4;
    int h  = blockIdx.x & 15;
    int i  = threadIdx.x;              // 128
    int t  = bc * CHUNKL + i;
    float d = softplusf(g_zx[(size_t)t * DINPROJ + 2176 + h] + dtb[h]);
    float A = -expf(Alog[h]);
    __shared__ float sh[CHUNKL];
    sh[i] = d * A;
    __syncthreads();
    #pragma unroll
    for (int off = 1; off < CHUNKL; off <<= 1){
        float v = (i >= off) ? sh[i - off] : 0.f;
        __syncthreads();
        sh[i] += v;
        __syncthreads();
    }
    g_dtv [t*NH + h] = d;
    g_acum[t*NH + h] = sh[i];
    if (i == CHUNKL - 1) g_dec[blockIdx.x] = expf(sh[i]);
}

// ---------------- scores[i][j] = Cm_i . Bm_j per (b,c) ----------------
__global__ void k_scores(){
    extern __shared__ float sm[];
    float* Csh = sm;                 // [128][65]
    float* Bsh = sm + 128*65;        // [128][65]
    int bc = blockIdx.x;
    int t0 = bc * CHUNKL;
    int tid = threadIdx.x;           // 256
    for (int idx = tid; idx < CHUNKL*DSTATE; idx += 256){
        int j = idx >> 6, n = idx & 63;
        Csh[j*65 + n] = g_xc[(size_t)(t0+j)*CONVDIM + DINNER + DSTATE + n];
        Bsh[j*65 + n] = g_xc[(size_t)(t0+j)*CONVDIM + DINNER + n];
    }
    __syncthreads();
    int i0 = (tid >> 4) * 8;
    int j0 = (tid & 15) * 8;
    float acc[8][8];
    #pragma unroll
    for (int r = 0; r < 8; r++)
        #pragma unroll
        for (int c = 0; c < 8; c++) acc[r][c] = 0.f;
    for (int n = 0; n < DSTATE; n++){
        float a[8], b[8];
        #pragma unroll
        for (int r = 0; r < 8; r++) a[r] = Csh[(i0+r)*65 + n];
        #pragma unroll
        for (int c = 0; c < 8; c++) b[c] = Bsh[(j0+c)*65 + n];
        #pragma unroll
        for (int r = 0; r < 8; r++)
            #pragma unroll
            for (int c = 0; c < 8; c++) acc[r][c] += a[r]*b[c];
    }
    float* out = g_sc + (size_t)bc * CHUNKL * CHUNKL;
    #pragma unroll
    for (int r = 0; r < 8; r++)
        #pragma unroll
        for (int c = 0; c < 8; c++)
            out[(i0+r)*CHUNKL + j0 + c] = acc[r][c];
}

// ---------------- y_diag per (b,c,h): masked weighted matmul ----------------
__global__ void k_ydiag(){
    int bc = blockIdx.x >> 4, h = blockIdx.x & 15;
    int i  = threadIdx.x;            // 128, one row each
    int t0 = bc * CHUNKL;
    __shared__ float xsh[CHUNKL*HD];
    __shared__ float ash[CHUNKL], dsh[CHUNKL];
    ash[i] = g_acum[(t0+i)*NH + h];
    dsh[i] = g_dtv [(t0+i)*NH + h];
    for (int idx = i; idx < CHUNKL*HD; idx += CHUNKL)
        xsh[idx] = g_xc[(size_t)(t0 + (idx >> 6))*CONVDIM + h*HD + (idx & 63)];
    __syncthreads();
    float acc[HD];
    #pragma unroll
    for (int p = 0; p < HD; p++) acc[p] = 0.f;
    const float* srow = g_sc + (size_t)bc * CHUNKL * CHUNKL + (size_t)i * CHUNKL;
    float ai = ash[i];
    for (int j = 0; j <= i; j++){
        float m = srow[j] * expf(ai - ash[j]) * dsh[j];
        const float* xr = &xsh[j*HD];
        #pragma unroll
        for (int p = 0; p < HD; p++) acc[p] += m * xr[p];
    }
    float* yrow = g_y + (size_t)(t0+i)*DINNER + h*HD;
    #pragma unroll
    for (int p = 0; p < HD; p++) yrow[p] = acc[p];
}

// ---------------- chunk states S[h][p][n] per (b,c,h) ----------------
__global__ void k_state(){
    extern __shared__ float sm[];
    float* xsh = sm;                  // [128][64]
    float* bsh = sm + CHUNKL*HD;      // [128][64]
    __shared__ float wsh[CHUNKL];
    int bc = blockIdx.x >> 4, h = blockIdx.x & 15;
    int t0 = bc * CHUNKL;
    int tid = threadIdx.x;            // 256
    for (int idx = tid; idx < CHUNKL*HD; idx += 256){
        int j = idx >> 6, q = idx & 63;
        xsh[idx] = g_xc[(size_t)(t0+j)*CONVDIM + h*HD + q];
        bsh[idx] = g_xc[(size_t)(t0+j)*CONVDIM + DINNER + q];
    }
    if (tid < CHUNKL){
        float alast = g_acum[(t0 + CHUNKL - 1)*NH + h];
        float aj    = g_acum[(t0 + tid)*NH + h];
        wsh[tid] = expf(alast - aj) * g_dtv[(t0 + tid)*NH + h];
    }
    __syncthreads();
    int p  = tid & 63;
    int n0 = (tid >> 6) << 4;         // 4 groups of 16 n
    float acc[16];
    #pragma unroll
    for (int k = 0; k < 16; k++) acc[k] = 0.f;
    for (int j = 0; j < CHUNKL; j++){
        float xw = xsh[j*HD + p] * wsh[j];
        const float* br = &bsh[j*HD + n0];
        #pragma unroll
        for (int k = 0; k < 16; k++) acc[k] += xw * br[k];
    }
    float* so = g_S + (size_t)blockIdx.x * (HD*DSTATE);
    #pragma unroll
    for (int k = 0; k < 16; k++) so[p*DSTATE + n0 + k] = acc[k];
}

// ---------------- sequential scan over chunks per (b,h) ----------------
__global__ void k_scan(){
    int b = blockIdx.x >> 4, h = blockIdx.x & 15;
    int tid = threadIdx.x;            // 256
    float st[16];
    #pragma unroll
    for (int k = 0; k < 16; k++) st[k] = 0.f;
    for (int c = 0; c < NCH; c++){
        int bch = (b*NCH + c)*NH + h;
        size_t base = (size_t)bch * (HD*DSTATE);
        float dc = g_dec[bch];
        #pragma unroll
        for (int k = 0; k < 16; k++){
            int idx = k*256 + tid;
            g_hs[base + idx] = st[k];
            st[k] = st[k]*dc + g_S[base + idx];
        }
    }
}

// ---------------- y_off + D*xh combine per (b,c,h) ----------------
__global__ void k_yoff(const float* __restrict__ Dp){
    int bc = blockIdx.x >> 4, h = blockIdx.x & 15;
    int i  = threadIdx.x;             // 128
    int t0 = bc * CHUNKL;
    __shared__ float hsh[HD*DSTATE];  // [p][n]
    const float* hbase = g_hs + (size_t)blockIdx.x * (HD*DSTATE);
    for (int idx = i; idx < HD*DSTATE; idx += CHUNKL) hsh[idx] = hbase[idx];
    float creg[DSTATE];
    const float* crow = g_xc + (size_t)(t0+i)*CONVDIM + DINNER + DSTATE;
    #pragma unroll
    for (int n = 0; n < DSTATE; n++) creg[n] = crow[n];
    __syncthreads();
    float ei = expf(g_acum[(t0+i)*NH + h]);
    float Dh = Dp[h];
    const float* xrow = g_xc + (size_t)(t0+i)*CONVDIM + h*HD;
    float* yrow = g_y + (size_t)(t0+i)*DINNER + h*HD;
    for (int p = 0; p < HD; p++){
        float a = 0.f;
        const float* hr = &hsh[p*DSTATE];
        #pragma unroll
        for (int n = 0; n < DSTATE; n++) a += creg[n] * hr[n];
        yrow[p] = yrow[p] + ei * a + Dh * xrow[p];
    }
}

// ---------------- gate: rmsnorm(y * silu(z)) * gnorm_w ----------------
__global__ void k_gate(const float* __restrict__ gw){
    int t = blockIdx.x;
    int tid = threadIdx.x;            // 256
    float v[4]; float ss = 0.f;
    #pragma unroll
    for (int k = 0; k < 4; k++){
        int d = k*256 + tid;
        float z = g_zx[(size_t)t*DINPROJ + d];
        float vv = g_y[(size_t)t*DINNER + d] * siluf(z);
        v[k] = vv; ss += vv*vv;
    }
    ss = blockReduceSum(ss);
    float rs = rsqrtf(ss / (float)DINNER + 1e-5f);
    #pragma unroll
    for (int k = 0; k < 4; k++){
        int d = k*256 + tid;
        g_yg[(size_t)t*DINNER + d] = v[k] * rs * gw[d];
    }
}

// ---------------- head ----------------
__global__ void k_head(const float* __restrict__ hw, const float* __restrict__ hb,
                       float* __restrict__ out){
    int idx = blockIdx.x * blockDim.x + threadIdx.x;
    if (idx >= NTOK * KOUT) return;
    int t = idx / KOUT, n = idx % KOUT;
    float acc = hb[n];
    const float* xr = g_xn + (size_t)t * DMODEL;
    for (int k = 0; k < DMODEL; k++) acc += xr[k] * hw[k*KOUT + n];
    out[idx] = acc;
}

// ---------------- host orchestration ----------------
extern "C" void kernel_launch(void* const* d_in, const int* in_sizes, int n_in,
                              void* d_out, int out_size){
    const float* x      = (const float*)d_in[0];
    const float* Wembed = (const float*)d_in[1];
    const float* rmsw   = (const float*)d_in[2];
    const float* inw    = (const float*)d_in[3];
    const float* convw  = (const float*)d_in[4];
    const float* convb  = (const float*)d_in[5];
    const float* dtb    = (const float*)d_in[6];
    const float* alog   = (const float*)d_in[7];
    const float* dparam = (const float*)d_in[8];
    const float* gnw    = (const float*)d_in[9];
    const float* outw   = (const float*)d_in[10];
    const float* fnw    = (const float*)d_in[11];
    const float* hw     = (const float*)d_in[12];
    const float* hb     = (const float*)d_in[13];
    float* out = (float*)d_out;

    // scratch addresses
    float *p_h, *p_xn, *p_zx, *p_hh, *p_yg;
    cudaGetSymbolAddress((void**)&p_h,  g_h);
    cudaGetSymbolAddress((void**)&p_xn, g_xn);
    cudaGetSymbolAddress((void**)&p_zx, g_zx);
    cudaGetSymbolAddress((void**)&p_yg, g_yg);
    p_hh = p_h;

    const int SCORES_SMEM = 2*128*65*4;   // 66560
    const int STATE_SMEM  = 2*CHUNKL*HD*4; // 65536
    cudaFuncSetAttribute(k_scores, cudaFuncAttributeMaxDynamicSharedMemorySize, SCORES_SMEM);
    cudaFuncSetAttribute(k_state,  cudaFuncAttributeMaxDynamicSharedMemorySize, STATE_SMEM);

    k_embed<<<(NTOK*DMODEL + 255)/256, 256>>>(x, Wembed);

    for (int l = 0; l < NLAYERS; l++){
        k_rmsnorm<<<NTOK, 256>>>(p_h, rmsw + (size_t)l*DMODEL, p_xn, DMODEL);
        k_gemm<<<dim3((DINPROJ+127)/128, NTOK/128), 256>>>(
            p_xn, inw + (size_t)l*DMODEL*DINPROJ, p_zx, nullptr,
            NTOK, DINPROJ, DMODEL);
        k_conv<<<(NTOK*CONVDIM + 255)/256, 256>>>(convw + (size_t)l*CONVDIM*DCONV,
                                                  convb + (size_t)l*CONVDIM);
        k_dt<<<NBC*NH, CHUNKL>>>(dtb + (size_t)l*NH, alog + (size_t)l*NH);
        k_scores<<<NBC, 256, SCORES_SMEM>>>();
        k_ydiag<<<NBC*NH, CHUNKL>>>();
        k_state<<<NBC*NH, 256, STATE_SMEM>>>();
        k_scan<<<BSZ*NH, 256>>>();
        k_yoff<<<NBC*NH, CHUNKL>>>(dparam + (size_t)l*NH);
        k_gate<<<NTOK, 256>>>(gnw + (size_t)l*DINNER);
        k_gemm<<<dim3((DMODEL+127)/128, NTOK/128), 256>>>(
            p_yg, outw + (size_t)l*DINNER*DMODEL, p_hh, p_hh,
            NTOK, DMODEL, DINNER);
    }

    k_rmsnorm<<<NTOK, 256>>>(p_h, fnw, p_xn, DMODEL);
    k_head<<<(NTOK*KOUT + 255)/256, 256>>>(hw, hb, out);
}

// round 3
// speedup vs baseline: 1.4868x; 1.4868x over previous
#include <cuda_runtime.h>
#include <cuda_bf16.h>
#include <math.h>
#include <stdint.h>

// ---------------- problem constants ----------------
#define BSZ     2
#define SEQL    2048
#define NTOK    (BSZ*SEQL)        // 4096
#define DMODEL  512
#define DINNER  1024
#define NH      16
#define HD      64
#define DSTATE  64
#define DCONV   4
#define CONVDIM 1152              // DINNER + 2*DSTATE
#define DINPROJ 2192              // 2*DINNER + 2*DSTATE + NH
#define NPAD_IN 2304              // DINPROJ padded to 128
#define NLAYERS 12
#define CHUNKL  128
#define NCH     16                // chunks per batch
#define NBC     (BSZ*NCH)         // 32
#define KOUT    30                // KLEN*3

// ---------------- scratch (static device globals; allocation-free) ----------
__device__ float g_h   [NTOK*DMODEL];
__device__ float g_xn  [NTOK*DMODEL];
__device__ float g_zx  [NTOK*DINPROJ];
__device__ float g_xc  [NTOK*CONVDIM];
__device__ float g_dtv [NTOK*NH];
__device__ float g_acum[NTOK*NH];
__device__ float g_dec [NBC*NH];
__device__ float g_sc  [NBC*CHUNKL*CHUNKL];
__device__ float g_y   [NTOK*DINNER];
__device__ float g_S   [NBC*NH*HD*DSTATE];
__device__ float g_hs  [NBC*NH*HD*DSTATE];
// bf16 hi/lo activations
__device__ __nv_bfloat16 g_xnh[NTOK*DMODEL];
__device__ __nv_bfloat16 g_xnl[NTOK*DMODEL];
__device__ __nv_bfloat16 g_ygh[NTOK*DINNER];
__device__ __nv_bfloat16 g_ygl[NTOK*DINNER];
// bf16 hi/lo transposed weights [layer][Npad][K]
__device__ __nv_bfloat16 g_wih[NLAYERS*NPAD_IN*DMODEL];
__device__ __nv_bfloat16 g_wil[NLAYERS*NPAD_IN*DMODEL];
__device__ __nv_bfloat16 g_woh[NLAYERS*DMODEL*DINNER];
__device__ __nv_bfloat16 g_wol[NLAYERS*DMODEL*DINNER];

// ---------------- small helpers ----------------
__device__ __forceinline__ uint32_t s2u(const void* p){
    uint32_t a;
    asm("{ .reg .u64 t; cvta.to.shared.u64 t, %1; cvt.u32.u64 %0, t; }" : "=r"(a) : "l"(p));
    return a;
}
__device__ __forceinline__ void ldsm4(uint32_t* r, uint32_t a){
    asm volatile("ldmatrix.sync.aligned.m8n8.x4.shared.b16 {%0,%1,%2,%3}, [%4];"
        : "=r"(r[0]), "=r"(r[1]), "=r"(r[2]), "=r"(r[3]) : "r"(a));
}
__device__ __forceinline__ void mma16816(float* d, const uint32_t* a, uint32_t b0, uint32_t b1){
    asm volatile("mma.sync.aligned.m16n8k16.row.col.f32.bf16.bf16.f32 "
        "{%0,%1,%2,%3}, {%4,%5,%6,%7}, {%8,%9}, {%0,%1,%2,%3};"
        : "+f"(d[0]), "+f"(d[1]), "+f"(d[2]), "+f"(d[3])
        : "r"(a[0]), "r"(a[1]), "r"(a[2]), "r"(a[3]), "r"(b0), "r"(b1));
}
__device__ __forceinline__ void cpasync16(uint32_t s, const void* g){
    uint64_t ga;
    asm("cvta.to.global.u64 %0, %1;" : "=l"(ga) : "l"(g));
    asm volatile("cp.async.cg.shared.global [%0], [%1], 16;" :: "r"(s), "l"(ga));
}
__device__ __forceinline__ void cpcommit(){ asm volatile("cp.async.commit_group;"); }
__device__ __forceinline__ void cpwait1(){ asm volatile("cp.async.wait_group 1;"); }

__device__ __forceinline__ float softplusf(float x){
    return (x > 20.f) ? x : log1pf(expf(x));
}
__device__ __forceinline__ float siluf(float x){
    return x / (1.f + expf(-x));
}
__device__ __forceinline__ float blockReduceSum(float v){
    __shared__ float sh[32];
    #pragma unroll
    for (int o = 16; o; o >>= 1) v += __shfl_xor_sync(0xffffffffu, v, o);
    int w = threadIdx.x >> 5;
    if ((threadIdx.x & 31) == 0) sh[w] = v;
    __syncthreads();
    int nw = blockDim.x >> 5;
    float r = (threadIdx.x < nw) ? sh[threadIdx.x] : 0.f;
    if (w == 0){
        #pragma unroll
        for (int o = 16; o; o >>= 1) r += __shfl_xor_sync(0xffffffffu, r, o);
        if (threadIdx.x == 0) sh[0] = r;
    }
    __syncthreads();
    return sh[0];
}

// ---------------- weight prep: transpose + bf16 hi/lo split ----------------
// W[K][N] -> Whi/Wlo[Npad][K] (zero pad n>=N)
__global__ void k_prep(const float* __restrict__ W, __nv_bfloat16* __restrict__ Whi,
                       __nv_bfloat16* __restrict__ Wlo, int K, int N, int Npad){
    int l = blockIdx.z;
    W   += (size_t)l * K * N;
    Whi += (size_t)l * Npad * K;
    Wlo += (size_t)l * Npad * K;
    __shared__ float t[32][33];
    int k0 = blockIdx.x * 32, n0 = blockIdx.y * 32;
    int tx = threadIdx.x, ty = threadIdx.y;
    for (int i = ty; i < 32; i += 8){
        float v = 0.f;
        if (n0 + tx < N) v = W[(size_t)(k0 + i) * N + n0 + tx];
        t[i][tx] = v;
    }
    __syncthreads();
    for (int i = ty; i < 32; i += 8){
        float v = t[tx][i];   // W[k0+tx][n0+i]
        __nv_bfloat16 hi = __float2bfloat16_rn(v);
        float lo = v - __bfloat162float(hi);
        Whi[(size_t)(n0 + i) * K + k0 + tx] = hi;
        Wlo[(size_t)(n0 + i) * K + k0 + tx] = __float2bfloat16_rn(lo);
    }
}

// ---------------- mma.sync bf16x3 GEMM ----------------
// C[M][N](+R) = (Ah+Al)[M][K] @ (Bh+Bl)^T, B stored [Npad][K].
// CTA 128x128 tile, 256 threads (8 warps of 64x32), k-chunk 32, double buffered.
// SMEM per buffer: A 128 rows x 128B (hi|lo), B 128 rows x 128B at +16384. Buffers at 0, 32768.
__global__ void __launch_bounds__(256, 1)
k_tgemm(const __nv_bfloat16* __restrict__ Ah, const __nv_bfloat16* __restrict__ Al,
        const __nv_bfloat16* __restrict__ Bh, const __nv_bfloat16* __restrict__ Bl,
        float* __restrict__ C, const float* __restrict__ R,
        int M, int N, int K)
{
    extern __shared__ char smc[];
    uint32_t sb = s2u(smc);
    int tid  = threadIdx.x;
    int lane = tid & 31, w = tid >> 5;
    int wm = w & 1, wn = w >> 1;
    int m0 = blockIdx.y * 128, n0 = blockIdx.x * 128;

    // loader assignment: thread -> row = tid>>1, part = tid&1 (0 hi, 1 lo)
    int lrow  = tid >> 1;
    int lpart = tid & 1;
    const __nv_bfloat16* gA = (lpart ? Al : Ah) + (size_t)(m0 + lrow) * K;
    const __nv_bfloat16* gB = (lpart ? Bl : Bh) + (size_t)(n0 + lrow) * K;
    uint32_t sArow = sb + (uint32_t)lrow * 128;
    uint32_t sBrow = sb + 16384u + (uint32_t)lrow * 128;
    uint32_t lsw[4];
    #pragma unroll
    for (int c = 0; c < 4; c++)
        lsw[c] = (uint32_t)(((lpart * 4 + c) ^ (lrow & 7)) * 16);

    float acc[4][4][4];
    #pragma unroll
    for (int mt = 0; mt < 4; mt++)
        #pragma unroll
        for (int nt = 0; nt < 4; nt++)
            #pragma unroll
            for (int e = 0; e < 4; e++) acc[mt][nt][e] = 0.f;

    // ldmatrix base offsets (row&7 == lane&7 for all tiles)
    uint32_t aoff = sb + (uint32_t)((wm * 64 + (lane & 15)) * 128);
    uint32_t boff = sb + 16384u + (uint32_t)((wn * 32 + (lane & 15)) * 128);
    uint32_t ct[2][2]; // [part][kh]
    #pragma unroll
    for (int part = 0; part < 2; part++)
        #pragma unroll
        for (int kh = 0; kh < 2; kh++)
            ct[part][kh] = (uint32_t)((((part * 4 + 2 * kh + (lane >> 4))) ^ (lane & 7)) * 16);

    int nit = K / 32;
    // prologue: load chunk 0 into buffer 0
    {
        const __nv_bfloat16* a = gA;
        const __nv_bfloat16* b = gB;
        #pragma unroll
        for (int c = 0; c < 4; c++) cpasync16(sArow + lsw[c], a + c * 8);
        #pragma unroll
        for (int c = 0; c < 4; c++) cpasync16(sBrow + lsw[c], b + c * 8);
    }
    cpcommit();

    for (int it = 0; it < nit; it++){
        if (it + 1 < nit){
            uint32_t bufo = (uint32_t)(((it + 1) & 1) * 32768);
            int k0 = (it + 1) * 32;
            const __nv_bfloat16* a = gA + k0;
            const __nv_bfloat16* b = gB + k0;
            #pragma unroll
            for (int c = 0; c < 4; c++) cpasync16(sArow + bufo + lsw[c], a + c * 8);
            #pragma unroll
            for (int c = 0; c < 4; c++) cpasync16(sBrow + bufo + lsw[c], b + c * 8);
        }
        cpcommit();
        cpwait1();
        __syncthreads();

        uint32_t bufo = (uint32_t)((it & 1) * 32768);
        #pragma unroll
        for (int kh = 0; kh < 2; kh++){
            uint32_t ah[4][4], al[4][4], bh[2][4], bl[2][4];
            #pragma unroll
            for (int mt = 0; mt < 4; mt++){
                uint32_t base = aoff + bufo + (uint32_t)(mt * 2048);
                ldsm4(ah[mt], base + ct[0][kh]);
                ldsm4(al[mt], base + ct[1][kh]);
            }
            #pragma unroll
            for (int g = 0; g < 2; g++){
                uint32_t base = boff + bufo + (uint32_t)(g * 2048);
                ldsm4(bh[g], base + ct[0][kh]);
                ldsm4(bl[g], base + ct[1][kh]);
            }
            #pragma unroll
            for (int mt = 0; mt < 4; mt++)
                #pragma unroll
                for (int nt = 0; nt < 4; nt++){
                    int g = nt >> 1, s = nt & 1;
                    mma16816(acc[mt][nt], ah[mt], bh[g][s], bh[g][s + 2]);
                    mma16816(acc[mt][nt], ah[mt], bl[g][s], bl[g][s + 2]);
                    mma16816(acc[mt][nt], al[mt], bh[g][s], bh[g][s + 2]);
                }
        }
        __syncthreads();
    }

    // epilogue
    #pragma unroll
    for (int mt = 0; mt < 4; mt++){
        int m = m0 + wm * 64 + mt * 16 + (lane >> 2);
        #pragma unroll
        for (int nt = 0; nt < 4; nt++){
            int col = n0 + wn * 32 + nt * 8 + (lane & 3) * 2;
            if (col < N){
                size_t i0 = (size_t)m * N + col;
                size_t i1 = (size_t)(m + 8) * N + col;
                float2 v0 = make_float2(acc[mt][nt][0], acc[mt][nt][1]);
                float2 v1 = make_float2(acc[mt][nt][2], acc[mt][nt][3]);
                if (R){
                    float2 r0 = *(const float2*)(R + i0);
                    float2 r1 = *(const float2*)(R + i1);
                    v0.x += r0.x; v0.y += r0.y;
                    v1.x += r1.x; v1.y += r1.y;
                }
                *(float2*)(C + i0) = v0;
                *(float2*)(C + i1) = v1;
            }
        }
    }
}

// ---------------- embedding: x@W_embed + nerf_pe ----------------
__global__ void k_embed(const float* __restrict__ x, const float* __restrict__ W){
    int idx = blockIdx.x * blockDim.x + threadIdx.x;
    if (idx >= NTOK * DMODEL) return;
    int t = idx / DMODEL, d = idx % DMODEL;
    float x0 = x[t*3+0]; if (x0 == -100.f) x0 = 0.f;
    float x1 = x[t*3+1]; if (x1 == -100.f) x1 = 0.f;
    float x2 = x[t*3+2]; if (x2 == -100.f) x2 = 0.f;
    float acc = x0 * W[0*DMODEL + d] + x1 * W[1*DMODEL + d] + x2 * W[2*DMODEL + d];
    if (d < 510){
        int c = d / 170, r = d % 170;
        float xv = (c == 0) ? x0 : ((c == 1) ? x1 : x2);
        float pe;
        if (r < 85) pe = sinf(xv * exp2f((float)r));
        else        pe = cosf(xv * exp2f((float)(r - 85)));
        acc += pe;
    }
    g_h[idx] = acc;
}

// ---------------- rmsnorm: fp32 out + bf16 hi/lo out ----------------
__global__ void k_rmsnorm(const float* __restrict__ x, const float* __restrict__ w,
                          float* __restrict__ o, __nv_bfloat16* __restrict__ oh,
                          __nv_bfloat16* __restrict__ ol, int D){
    int t = blockIdx.x;
    const float* xr = x + (size_t)t * D;
    float ss = 0.f;
    for (int d = threadIdx.x; d < D; d += blockDim.x){
        float v = xr[d];
        ss += v * v;
    }
    ss = blockReduceSum(ss);
    float rs = rsqrtf(ss / (float)D + 1e-5f);
    for (int d = threadIdx.x; d < D; d += blockDim.x){
        float v = xr[d] * rs * w[d];
        o[(size_t)t * D + d] = v;
        __nv_bfloat16 hi = __float2bfloat16_rn(v);
        oh[(size_t)t * D + d] = hi;
        ol[(size_t)t * D + d] = __float2bfloat16_rn(v - __bfloat162float(hi));
    }
}

// ---------------- causal depthwise conv + silu ----------------
__global__ void k_conv(const float* __restrict__ cw, const float* __restrict__ cb){
    int idx = blockIdx.x * blockDim.x + threadIdx.x;
    if (idx >= NTOK * CONVDIM) return;
    int t = idx / CONVDIM, ch = idx % CONVDIM;
    int l = t % SEQL;
    float acc = cb[ch];
    #pragma unroll
    for (int k = 0; k < DCONV; k++){
        int l2 = l + k - (DCONV - 1);
        if (l2 >= 0)
            acc += g_zx[(size_t)(t + l2 - l) * DINPROJ + DINNER + ch] * cw[ch*DCONV + k];
    }
    g_xc[idx] = siluf(acc);
}

// ---------------- dt prep ----------------
__global__ void k_dt(const float* __restrict__ dtb, const float* __restrict__ Alog){
    int bc = blockIdx.x >> 4;
    int h  = blockIdx.x & 15;
    int i  = threadIdx.x;              // 128
    int t  = bc * CHUNKL + i;
    float d = softplusf(g_zx[(size_t)t * DINPROJ + 2176 + h] + dtb[h]);
    float A = -expf(Alog[h]);
    __shared__ float sh[CHUNKL];
    sh[i] = d * A;
    __syncthreads();
    #pragma unroll
    for (int off = 1; off < CHUNKL; off <<= 1){
        float v = (i >= off) ? sh[i - off] : 0.f;
        __syncthreads();
        sh[i] += v;
        __syncthreads();
    }
    g_dtv [t*NH + h] = d;
    g_acum[t*NH + h] = sh[i];
    if (i == CHUNKL - 1) g_dec[blockIdx.x] = expf(sh[i]);
}

// ---------------- scores ----------------
__global__ void k_scores(){
    extern __shared__ float smf[];
    float* Csh = smf;
    float* Bsh = smf + 128*65;
    int bc = blockIdx.x;
    int t0 = bc * CHUNKL;
    int tid = threadIdx.x;
    for (int idx = tid; idx < CHUNKL*DSTATE; idx += 256){
        int j = idx >> 6, n = idx & 63;
        Csh[j*65 + n] = g_xc[(size_t)(t0+j)*CONVDIM + DINNER + DSTATE + n];
        Bsh[j*65 + n] = g_xc[(size_t)(t0+j)*CONVDIM + DINNER + n];
    }
    __syncthreads();
    int i0 = (tid >> 4) * 8;
    int j0 = (tid & 15) * 8;
    float acc[8][8];
    #pragma unroll
    for (int r = 0; r < 8; r++)
        #pragma unroll
        for (int c = 0; c < 8; c++) acc[r][c] = 0.f;
    for (int n = 0; n < DSTATE; n++){
        float a[8], b[8];
        #pragma unroll
        for (int r = 0; r < 8; r++) a[r] = Csh[(i0+r)*65 + n];
        #pragma unroll
        for (int c = 0; c < 8; c++) b[c] = Bsh[(j0+c)*65 + n];
        #pragma unroll
        for (int r = 0; r < 8; r++)
            #pragma unroll
            for (int c = 0; c < 8; c++) acc[r][c] += a[r]*b[c];
    }
    float* out = g_sc + (size_t)bc * CHUNKL * CHUNKL;
    #pragma unroll
    for (int r = 0; r < 8; r++)
        #pragma unroll
        for (int c = 0; c < 8; c++)
            out[(i0+r)*CHUNKL + j0 + c] = acc[r][c];
}

// ---------------- y_diag ----------------
__global__ void k_ydiag(){
    int bc = blockIdx.x >> 4, h = blockIdx.x & 15;
    int i  = threadIdx.x;
    int t0 = bc * CHUNKL;
    __shared__ float xsh[CHUNKL*HD];
    __shared__ float ash[CHUNKL], dsh[CHUNKL];
    ash[i] = g_acum[(t0+i)*NH + h];
    dsh[i] = g_dtv [(t0+i)*NH + h];
    for (int idx = i; idx < CHUNKL*HD; idx += CHUNKL)
        xsh[idx] = g_xc[(size_t)(t0 + (idx >> 6))*CONVDIM + h*HD + (idx & 63)];
    __syncthreads();
    float acc[HD];
    #pragma unroll
    for (int p = 0; p < HD; p++) acc[p] = 0.f;
    const float* srow = g_sc + (size_t)bc * CHUNKL * CHUNKL + (size_t)i * CHUNKL;
    float ai = ash[i];
    for (int j = 0; j <= i; j++){
        float m = srow[j] * expf(ai - ash[j]) * dsh[j];
        const float* xr = &xsh[j*HD];
        #pragma unroll
        for (int p = 0; p < HD; p++) acc[p] += m * xr[p];
    }
    float* yrow = g_y + (size_t)(t0+i)*DINNER + h*HD;
    #pragma unroll
    for (int p = 0; p < HD; p++) yrow[p] = acc[p];
}

// ---------------- chunk states ----------------
__global__ void k_state(){
    extern __shared__ float smf[];
    float* xsh = smf;
    float* bsh = smf + CHUNKL*HD;
    __shared__ float wsh[CHUNKL];
    int bc = blockIdx.x >> 4, h = blockIdx.x & 15;
    int t0 = bc * CHUNKL;
    int tid = threadIdx.x;
    for (int idx = tid; idx < CHUNKL*HD; idx += 256){
        int j = idx >> 6, q = idx & 63;
        xsh[idx] = g_xc[(size_t)(t0+j)*CONVDIM + h*HD + q];
        bsh[idx] = g_xc[(size_t)(t0+j)*CONVDIM + DINNER + q];
    }
    if (tid < CHUNKL){
        float alast = g_acum[(t0 + CHUNKL - 1)*NH + h];
        float aj    = g_acum[(t0 + tid)*NH + h];
        wsh[tid] = expf(alast - aj) * g_dtv[(t0 + tid)*NH + h];
    }
    __syncthreads();
    int p  = tid & 63;
    int n0 = (tid >> 6) << 4;
    float acc[16];
    #pragma unroll
    for (int k = 0; k < 16; k++) acc[k] = 0.f;
    for (int j = 0; j < CHUNKL; j++){
        float xw = xsh[j*HD + p] * wsh[j];
        const float* br = &bsh[j*HD + n0];
        #pragma unroll
        for (int k = 0; k < 16; k++) acc[k] += xw * br[k];
    }
    float* so = g_S + (size_t)blockIdx.x * (HD*DSTATE);
    #pragma unroll
    for (int k = 0; k < 16; k++) so[p*DSTATE + n0 + k] = acc[k];
}

// ---------------- scan ----------------
__global__ void k_scan(){
    int b = blockIdx.x >> 4, h = blockIdx.x & 15;
    int tid = threadIdx.x;
    float st[16];
    #pragma unroll
    for (int k = 0; k < 16; k++) st[k] = 0.f;
    for (int c = 0; c < NCH; c++){
        int bch = (b*NCH + c)*NH + h;
        size_t base = (size_t)bch * (HD*DSTATE);
        float dc = g_dec[bch];
        #pragma unroll
        for (int k = 0; k < 16; k++){
            int idx = k*256 + tid;
            g_hs[base + idx] = st[k];
            st[k] = st[k]*dc + g_S[base + idx];
        }
    }
}

// ---------------- y_off + D*xh ----------------
__global__ void k_yoff(const float* __restrict__ Dp){
    int bc = blockIdx.x >> 4, h = blockIdx.x & 15;
    int i  = threadIdx.x;
    int t0 = bc * CHUNKL;
    __shared__ float hsh[HD*DSTATE];
    const float* hbase = g_hs + (size_t)blockIdx.x * (HD*DSTATE);
    for (int idx = i; idx < HD*DSTATE; idx += CHUNKL) hsh[idx] = hbase[idx];
    float creg[DSTATE];
    const float* crow = g_xc + (size_t)(t0+i)*CONVDIM + DINNER + DSTATE;
    #pragma unroll
    for (int n = 0; n < DSTATE; n++) creg[n] = crow[n];
    __syncthreads();
    float ei = expf(g_acum[(t0+i)*NH + h]);
    float Dh = Dp[h];
    const float* xrow = g_xc + (size_t)(t0+i)*CONVDIM + h*HD;
    float* yrow = g_y + (size_t)(t0+i)*DINNER + h*HD;
    for (int p = 0; p < HD; p++){
        float a = 0.f;
        const float* hr = &hsh[p*DSTATE];
        #pragma unroll
        for (int n = 0; n < DSTATE; n++) a += creg[n] * hr[n];
        yrow[p] = yrow[p] + ei * a + Dh * xrow[p];
    }
}

// ---------------- gate: rmsnorm(y*silu(z))*gw -> bf16 hi/lo ----------------
__global__ void k_gate(const float* __restrict__ gw){
    int t = blockIdx.x;
    int tid = threadIdx.x;
    float v[4]; float ss = 0.f;
    #pragma unroll
    for (int k = 0; k < 4; k++){
        int d = k*256 + tid;
        float z = g_zx[(size_t)t*DINPROJ + d];
        float vv = g_y[(size_t)t*DINNER + d] * siluf(z);
        v[k] = vv; ss += vv*vv;
    }
    ss = blockReduceSum(ss);
    float rs = rsqrtf(ss / (float)DINNER + 1e-5f);
    #pragma unroll
    for (int k = 0; k < 4; k++){
        int d = k*256 + tid;
        float o = v[k] * rs * gw[d];
        __nv_bfloat16 hi = __float2bfloat16_rn(o);
        g_ygh[(size_t)t*DINNER + d] = hi;
        g_ygl[(size_t)t*DINNER + d] = __float2bfloat16_rn(o - __bfloat162float(hi));
    }
}

// ---------------- head ----------------
__global__ void k_head(const float* __restrict__ hw, const float* __restrict__ hb,
                       float* __restrict__ out){
    int idx = blockIdx.x * blockDim.x + threadIdx.x;
    if (idx >= NTOK * KOUT) return;
    int t = idx / KOUT, n = idx % KOUT;
    float acc = hb[n];
    const float* xr = g_xn + (size_t)t * DMODEL;
    for (int k = 0; k < DMODEL; k++) acc += xr[k] * hw[k*KOUT + n];
    out[idx] = acc;
}

// ---------------- host orchestration ----------------
extern "C" void kernel_launch(void* const* d_in, const int* in_sizes, int n_in,
                              void* d_out, int out_size){
    const float* x      = (const float*)d_in[0];
    const float* Wembed = (const float*)d_in[1];
    const float* rmsw   = (const float*)d_in[2];
    const float* inw    = (const float*)d_in[3];
    const float* convw  = (const float*)d_in[4];
    const float* convb  = (const float*)d_in[5];
    const float* dtb    = (const float*)d_in[6];
    const float* alog   = (const float*)d_in[7];
    const float* dparam = (const float*)d_in[8];
    const float* gnw    = (const float*)d_in[9];
    const float* outw   = (const float*)d_in[10];
    const float* fnw    = (const float*)d_in[11];
    const float* hw     = (const float*)d_in[12];
    const float* hb     = (const float*)d_in[13];
    float* out = (float*)d_out;

    float *p_h, *p_xn, *p_zx;
    cudaGetSymbolAddress((void**)&p_h,  g_h);
    cudaGetSymbolAddress((void**)&p_xn, g_xn);
    cudaGetSymbolAddress((void**)&p_zx, g_zx);
    __nv_bfloat16 *p_xnh, *p_xnl, *p_ygh, *p_ygl;
    cudaGetSymbolAddress((void**)&p_xnh, g_xnh);
    cudaGetSymbolAddress((void**)&p_xnl, g_xnl);
    cudaGetSymbolAddress((void**)&p_ygh, g_ygh);
    cudaGetSymbolAddress((void**)&p_ygl, g_ygl);
    __nv_bfloat16 *p_wih, *p_wil, *p_woh, *p_wol;
    cudaGetSymbolAddress((void**)&p_wih, g_wih);
    cudaGetSymbolAddress((void**)&p_wil, g_wil);
    cudaGetSymbolAddress((void**)&p_woh, g_woh);
    cudaGetSymbolAddress((void**)&p_wol, g_wol);

    const int SCORES_SMEM = 2*128*65*4;
    const int STATE_SMEM  = 2*CHUNKL*HD*4;
    const int TG_SMEM     = 65536;
    cudaFuncSetAttribute(k_scores, cudaFuncAttributeMaxDynamicSharedMemorySize, SCORES_SMEM);
    cudaFuncSetAttribute(k_state,  cudaFuncAttributeMaxDynamicSharedMemorySize, STATE_SMEM);
    cudaFuncSetAttribute(k_tgemm,  cudaFuncAttributeMaxDynamicSharedMemorySize, TG_SMEM);

    // weight preprocessing (deterministic, graph-capturable)
    k_prep<<<dim3(DMODEL/32, NPAD_IN/32, NLAYERS), dim3(32,8)>>>(
        inw, p_wih, p_wil, DMODEL, DINPROJ, NPAD_IN);
    k_prep<<<dim3(DINNER/32, DMODEL/32, NLAYERS), dim3(32,8)>>>(
        outw, p_woh, p_wol, DINNER, DMODEL, DMODEL);

    k_embed<<<(NTOK*DMODEL + 255)/256, 256>>>(x, Wembed);

    for (int l = 0; l < NLAYERS; l++){
        k_rmsnorm<<<NTOK, 256>>>(p_h, rmsw + (size_t)l*DMODEL, p_xn, p_xnh, p_xnl, DMODEL);
        k_tgemm<<<dim3(NPAD_IN/128, NTOK/128), 256, TG_SMEM>>>(
            p_xnh, p_xnl,
            p_wih + (size_t)l*NPAD_IN*DMODEL, p_wil + (size_t)l*NPAD_IN*DMODEL,
            p_zx, nullptr, NTOK, DINPROJ, DMODEL);
        k_conv<<<(NTOK*CONVDIM + 255)/256, 256>>>(convw + (size_t)l*CONVDIM*DCONV,
                                                  convb + (size_t)l*CONVDIM);
        k_dt<<<NBC*NH, CHUNKL>>>(dtb + (size_t)l*NH, alog + (size_t)l*NH);
        k_scores<<<NBC, 256, SCORES_SMEM>>>();
        k_ydiag<<<NBC*NH, CHUNKL>>>();
        k_state<<<NBC*NH, 256, STATE_SMEM>>>();
        k_scan<<<BSZ*NH, 256>>>();
        k_yoff<<<NBC*NH, CHUNKL>>>(dparam + (size_t)l*NH);
        k_gate<<<NTOK, 256>>>(gnw + (size_t)l*DINNER);
        k_tgemm<<<dim3(DMODEL/128, NTOK/128), 256, TG_SMEM>>>(
            p_ygh, p_ygl,
            p_woh + (size_t)l*DMODEL*DINNER, p_wol + (size_t)l*DMODEL*DINNER,
            p_h, p_h, NTOK, DMODEL, DINNER);
    }

    k_rmsnorm<<<NTOK, 256>>>(p_h, fnw, p_xn, p_xnh, p_xnl, DMODEL);
    k_head<<<(NTOK*KOUT + 255)/256, 256>>>(hw, hb, out);
}

// round 4
// speedup vs baseline: 1.5160x; 1.0196x over previous
#include <cuda_runtime.h>
#include <cuda_bf16.h>
#include <math.h>
#include <stdint.h>

// ---------------- problem constants ----------------
#define BSZ     2
#define SEQL    2048
#define NTOK    (BSZ*SEQL)        // 4096
#define DMODEL  512
#define DINNER  1024
#define NH      16
#define HD      64
#define DSTATE  64
#define DCONV   4
#define CONVDIM 1152              // DINNER + 2*DSTATE
#define DINPROJ 2192              // 2*DINNER + 2*DSTATE + NH
#define NPAD_IN 2304              // DINPROJ padded to 128
#define NLAYERS 12
#define CHUNKL  128
#define NCH     16                // chunks per batch
#define NBC     (BSZ*NCH)         // 32
#define KOUT    30                // KLEN*3

// ---------------- scratch (static device globals; allocation-free) ----------
__device__ float g_h   [NTOK*DMODEL];
__device__ float g_xn  [NTOK*DMODEL];
__device__ float g_zx  [NTOK*DINPROJ];
__device__ float g_xc  [NTOK*CONVDIM];
__device__ float g_dtv [NTOK*NH];
__device__ float g_acum[NTOK*NH];
__device__ float g_dec [NBC*NH];
__device__ float g_sc  [NBC*CHUNKL*CHUNKL];
__device__ float g_y   [NTOK*DINNER];
__device__ float g_S   [NBC*NH*HD*DSTATE];
__device__ float g_hs  [NBC*NH*HD*DSTATE];
// bf16 hi/lo activations
__device__ __nv_bfloat16 g_xnh[NTOK*DMODEL];
__device__ __nv_bfloat16 g_xnl[NTOK*DMODEL];
__device__ __nv_bfloat16 g_ygh[NTOK*DINNER];
__device__ __nv_bfloat16 g_ygl[NTOK*DINNER];
// bf16 hi/lo transposed weights [layer][Npad][K]
__device__ __nv_bfloat16 g_wih[NLAYERS*NPAD_IN*DMODEL];
__device__ __nv_bfloat16 g_wil[NLAYERS*NPAD_IN*DMODEL];
__device__ __nv_bfloat16 g_woh[NLAYERS*DMODEL*DINNER];
__device__ __nv_bfloat16 g_wol[NLAYERS*DMODEL*DINNER];

// ---------------- small helpers ----------------
__device__ __forceinline__ uint32_t s2u(const void* p){
    uint32_t a;
    asm("{ .reg .u64 t; cvta.to.shared.u64 t, %1; cvt.u32.u64 %0, t; }" : "=r"(a) : "l"(p));
    return a;
}
__device__ __forceinline__ void ldsm4(uint32_t* r, uint32_t a){
    asm volatile("ldmatrix.sync.aligned.m8n8.x4.shared.b16 {%0,%1,%2,%3}, [%4];"
        : "=r"(r[0]), "=r"(r[1]), "=r"(r[2]), "=r"(r[3]) : "r"(a));
}
__device__ __forceinline__ void mma16816(float* d, const uint32_t* a, uint32_t b0, uint32_t b1){
    asm volatile("mma.sync.aligned.m16n8k16.row.col.f32.bf16.bf16.f32 "
        "{%0,%1,%2,%3}, {%4,%5,%6,%7}, {%8,%9}, {%0,%1,%2,%3};"
        : "+f"(d[0]), "+f"(d[1]), "+f"(d[2]), "+f"(d[3])
        : "r"(a[0]), "r"(a[1]), "r"(a[2]), "r"(a[3]), "r"(b0), "r"(b1));
}
__device__ __forceinline__ void cpasync16(uint32_t s, const void* g){
    uint64_t ga;
    asm("cvta.to.global.u64 %0, %1;" : "=l"(ga) : "l"(g));
    asm volatile("cp.async.cg.shared.global [%0], [%1], 16;" :: "r"(s), "l"(ga));
}
__device__ __forceinline__ void cpcommit(){ asm volatile("cp.async.commit_group;"); }
__device__ __forceinline__ void cpwait1(){ asm volatile("cp.async.wait_group 1;"); }

__device__ __forceinline__ float softplusf(float x){
    return (x > 20.f) ? x : log1pf(expf(x));
}
__device__ __forceinline__ float siluf(float x){
    return x / (1.f + expf(-x));
}
__device__ __forceinline__ float blockReduceSum(float v){
    __shared__ float sh[32];
    #pragma unroll
    for (int o = 16; o; o >>= 1) v += __shfl_xor_sync(0xffffffffu, v, o);
    int w = threadIdx.x >> 5;
    if ((threadIdx.x & 31) == 0) sh[w] = v;
    __syncthreads();
    int nw = blockDim.x >> 5;
    float r = (threadIdx.x < nw) ? sh[threadIdx.x] : 0.f;
    if (w == 0){
        #pragma unroll
        for (int o = 16; o; o >>= 1) r += __shfl_xor_sync(0xffffffffu, r, o);
        if (threadIdx.x == 0) sh[0] = r;
    }
    __syncthreads();
    return sh[0];
}

// ---------------- weight prep: transpose + bf16 hi/lo split ----------------
__global__ void k_prep(const float* __restrict__ W, __nv_bfloat16* __restrict__ Whi,
                       __nv_bfloat16* __restrict__ Wlo, int K, int N, int Npad){
    int l = blockIdx.z;
    W   += (size_t)l * K * N;
    Whi += (size_t)l * Npad * K;
    Wlo += (size_t)l * Npad * K;
    __shared__ float t[32][33];
    int k0 = blockIdx.x * 32, n0 = blockIdx.y * 32;
    int tx = threadIdx.x, ty = threadIdx.y;
    for (int i = ty; i < 32; i += 8){
        float v = 0.f;
        if (n0 + tx < N) v = W[(size_t)(k0 + i) * N + n0 + tx];
        t[i][tx] = v;
    }
    __syncthreads();
    for (int i = ty; i < 32; i += 8){
        float v = t[tx][i];   // W[k0+tx][n0+i]
        __nv_bfloat16 hi = __float2bfloat16_rn(v);
        float lo = v - __bfloat162float(hi);
        Whi[(size_t)(n0 + i) * K + k0 + tx] = hi;
        Wlo[(size_t)(n0 + i) * K + k0 + tx] = __float2bfloat16_rn(lo);
    }
}

// ---------------- mma.sync bf16x3 GEMM, 3-stage pipeline, occ 2 ----------------
// C[M][N](+R) = (Ah+Al)[M][K] @ (Bh+Bl)^T, B stored [Npad][K].
// CTA 128x128 tile, 256 threads (8 warps of 64x32), k-chunk 32.
// 3 smem buffers of 32KB: A rows 128x128B at +0, B at +16384. One sync per iter.
__global__ void __launch_bounds__(256, 2)
k_tgemm(const __nv_bfloat16* __restrict__ Ah, const __nv_bfloat16* __restrict__ Al,
        const __nv_bfloat16* __restrict__ Bh, const __nv_bfloat16* __restrict__ Bl,
        float* __restrict__ C, const float* __restrict__ R,
        int M, int N, int K)
{
    extern __shared__ char smc[];
    uint32_t sb = s2u(smc);
    int tid  = threadIdx.x;
    int lane = tid & 31, w = tid >> 5;
    int wm = w & 1, wn = w >> 1;
    int m0 = blockIdx.y * 128, n0 = blockIdx.x * 128;

    // loader: thread -> row = tid>>1, part = tid&1 (0 hi, 1 lo)
    int lrow  = tid >> 1;
    int lpart = tid & 1;
    const __nv_bfloat16* gA = (lpart ? Al : Ah) + (size_t)(m0 + lrow) * K;
    const __nv_bfloat16* gB = (lpart ? Bl : Bh) + (size_t)(n0 + lrow) * K;
    uint32_t sArow = sb + (uint32_t)lrow * 128;
    uint32_t sBrow = sb + 16384u + (uint32_t)lrow * 128;
    uint32_t lsw[4];
    #pragma unroll
    for (int c = 0; c < 4; c++)
        lsw[c] = (uint32_t)(((lpart * 4 + c) ^ (lrow & 7)) * 16);

    float acc[4][4][4];
    #pragma unroll
    for (int mt = 0; mt < 4; mt++)
        #pragma unroll
        for (int nt = 0; nt < 4; nt++)
            #pragma unroll
            for (int e = 0; e < 4; e++) acc[mt][nt][e] = 0.f;

    uint32_t aoff = sb + (uint32_t)((wm * 64 + (lane & 15)) * 128);
    uint32_t boff = sb + 16384u + (uint32_t)((wn * 32 + (lane & 15)) * 128);
    uint32_t ct[2][2]; // [part][kh]
    #pragma unroll
    for (int part = 0; part < 2; part++)
        #pragma unroll
        for (int kh = 0; kh < 2; kh++)
            ct[part][kh] = (uint32_t)((((part * 4 + 2 * kh + (lane >> 4))) ^ (lane & 7)) * 16);

    int nit = K / 32;
    // prologue: prefetch chunk 0 -> buf0, chunk 1 -> buf1
    {
        #pragma unroll
        for (int c = 0; c < 4; c++) cpasync16(sArow + lsw[c], gA + c * 8);
        #pragma unroll
        for (int c = 0; c < 4; c++) cpasync16(sBrow + lsw[c], gB + c * 8);
        cpcommit();
        if (nit > 1){
            #pragma unroll
            for (int c = 0; c < 4; c++) cpasync16(sArow + 32768u + lsw[c], gA + 32 + c * 8);
            #pragma unroll
            for (int c = 0; c < 4; c++) cpasync16(sBrow + 32768u + lsw[c], gB + 32 + c * 8);
        }
        cpcommit();
    }

    int cur = 0, nxt = 2;   // buffer indices: compute buf, prefetch buf
    for (int it = 0; it < nit; it++){
        cpwait1();
        __syncthreads();
        if (it + 2 < nit){
            uint32_t bo = (uint32_t)nxt * 32768u;
            int k0 = (it + 2) * 32;
            #pragma unroll
            for (int c = 0; c < 4; c++) cpasync16(sArow + bo + lsw[c], gA + k0 + c * 8);
            #pragma unroll
            for (int c = 0; c < 4; c++) cpasync16(sBrow + bo + lsw[c], gB + k0 + c * 8);
        }
        cpcommit();

        uint32_t bufo = (uint32_t)cur * 32768u;
        #pragma unroll
        for (int kh = 0; kh < 2; kh++){
            uint32_t ah[4][4], al[4][4], bh[2][4], bl[2][4];
            #pragma unroll
            for (int mt = 0; mt < 4; mt++){
                uint32_t base = aoff + bufo + (uint32_t)(mt * 2048);
                ldsm4(ah[mt], base + ct[0][kh]);
                ldsm4(al[mt], base + ct[1][kh]);
            }
            #pragma unroll
            for (int g = 0; g < 2; g++){
                uint32_t base = boff + bufo + (uint32_t)(g * 2048);
                ldsm4(bh[g], base + ct[0][kh]);
                ldsm4(bl[g], base + ct[1][kh]);
            }
            #pragma unroll
            for (int mt = 0; mt < 4; mt++)
                #pragma unroll
                for (int nt = 0; nt < 4; nt++){
                    int g = nt >> 1, s = nt & 1;
                    mma16816(acc[mt][nt], ah[mt], bh[g][s], bh[g][s + 2]);
                    mma16816(acc[mt][nt], ah[mt], bl[g][s], bl[g][s + 2]);
                    mma16816(acc[mt][nt], al[mt], bh[g][s], bh[g][s + 2]);
                }
        }
        if (++cur == 3) cur = 0;
        if (++nxt == 3) nxt = 0;
    }

    // epilogue
    #pragma unroll
    for (int mt = 0; mt < 4; mt++){
        int m = m0 + wm * 64 + mt * 16 + (lane >> 2);
        #pragma unroll
        for (int nt = 0; nt < 4; nt++){
            int col = n0 + wn * 32 + nt * 8 + (lane & 3) * 2;
            if (col < N){
                size_t i0 = (size_t)m * N + col;
                size_t i1 = (size_t)(m + 8) * N + col;
                float2 v0 = make_float2(acc[mt][nt][0], acc[mt][nt][1]);
                float2 v1 = make_float2(acc[mt][nt][2], acc[mt][nt][3]);
                if (R){
                    float2 r0 = *(const float2*)(R + i0);
                    float2 r1 = *(const float2*)(R + i1);
                    v0.x += r0.x; v0.y += r0.y;
                    v1.x += r1.x; v1.y += r1.y;
                }
                *(float2*)(C + i0) = v0;
                *(float2*)(C + i1) = v1;
            }
        }
    }
}

// ---------------- embedding: x@W_embed + nerf_pe ----------------
__global__ void k_embed(const float* __restrict__ x, const float* __restrict__ W){
    int idx = blockIdx.x * blockDim.x + threadIdx.x;
    if (idx >= NTOK * DMODEL) return;
    int t = idx / DMODEL, d = idx % DMODEL;
    float x0 = x[t*3+0]; if (x0 == -100.f) x0 = 0.f;
    float x1 = x[t*3+1]; if (x1 == -100.f) x1 = 0.f;
    float x2 = x[t*3+2]; if (x2 == -100.f) x2 = 0.f;
    float acc = x0 * W[0*DMODEL + d] + x1 * W[1*DMODEL + d] + x2 * W[2*DMODEL + d];
    if (d < 510){
        int c = d / 170, r = d % 170;
        float xv = (c == 0) ? x0 : ((c == 1) ? x1 : x2);
        float pe;
        if (r < 85) pe = sinf(xv * exp2f((float)r));
        else        pe = cosf(xv * exp2f((float)(r - 85)));
        acc += pe;
    }
    g_h[idx] = acc;
}

// ---------------- rmsnorm: fp32 out + bf16 hi/lo out ----------------
__global__ void k_rmsnorm(const float* __restrict__ x, const float* __restrict__ w,
                          float* __restrict__ o, __nv_bfloat16* __restrict__ oh,
                          __nv_bfloat16* __restrict__ ol, int D){
    int t = blockIdx.x;
    const float* xr = x + (size_t)t * D;
    float ss = 0.f;
    for (int d = threadIdx.x; d < D; d += blockDim.x){
        float v = xr[d];
        ss += v * v;
    }
    ss = blockReduceSum(ss);
    float rs = rsqrtf(ss / (float)D + 1e-5f);
    for (int d = threadIdx.x; d < D; d += blockDim.x){
        float v = xr[d] * rs * w[d];
        o[(size_t)t * D + d] = v;
        __nv_bfloat16 hi = __float2bfloat16_rn(v);
        oh[(size_t)t * D + d] = hi;
        ol[(size_t)t * D + d] = __float2bfloat16_rn(v - __bfloat162float(hi));
    }
}

// ---------------- causal depthwise conv + silu ----------------
__global__ void k_conv(const float* __restrict__ cw, const float* __restrict__ cb){
    int idx = blockIdx.x * blockDim.x + threadIdx.x;
    if (idx >= NTOK * CONVDIM) return;
    int t = idx / CONVDIM, ch = idx % CONVDIM;
    int l = t % SEQL;
    float acc = cb[ch];
    #pragma unroll
    for (int k = 0; k < DCONV; k++){
        int l2 = l + k - (DCONV - 1);
        if (l2 >= 0)
            acc += g_zx[(size_t)(t + l2 - l) * DINPROJ + DINNER + ch] * cw[ch*DCONV + k];
    }
    g_xc[idx] = siluf(acc);
}

// ---------------- dt prep ----------------
__global__ void k_dt(const float* __restrict__ dtb, const float* __restrict__ Alog){
    int bc = blockIdx.x >> 4;
    int h  = blockIdx.x & 15;
    int i  = threadIdx.x;              // 128
    int t  = bc * CHUNKL + i;
    float d = softplusf(g_zx[(size_t)t * DINPROJ + 2176 + h] + dtb[h]);
    float A = -expf(Alog[h]);
    __shared__ float sh[CHUNKL];
    sh[i] = d * A;
    __syncthreads();
    #pragma unroll
    for (int off = 1; off < CHUNKL; off <<= 1){
        float v = (i >= off) ? sh[i - off] : 0.f;
        __syncthreads();
        sh[i] += v;
        __syncthreads();
    }
    g_dtv [t*NH + h] = d;
    g_acum[t*NH + h] = sh[i];
    if (i == CHUNKL - 1) g_dec[blockIdx.x] = expf(sh[i]);
}

// ---------------- scores ----------------
__global__ void k_scores(){
    extern __shared__ float smf[];
    float* Csh = smf;
    float* Bsh = smf + 128*65;
    int bc = blockIdx.x;
    int t0 = bc * CHUNKL;
    int tid = threadIdx.x;
    for (int idx = tid; idx < CHUNKL*DSTATE; idx += 256){
        int j = idx >> 6, n = idx & 63;
        Csh[j*65 + n] = g_xc[(size_t)(t0+j)*CONVDIM + DINNER + DSTATE + n];
        Bsh[j*65 + n] = g_xc[(size_t)(t0+j)*CONVDIM + DINNER + n];
    }
    __syncthreads();
    int i0 = (tid >> 4) * 8;
    int j0 = (tid & 15) * 8;
    float acc[8][8];
    #pragma unroll
    for (int r = 0; r < 8; r++)
        #pragma unroll
        for (int c = 0; c < 8; c++) acc[r][c] = 0.f;
    for (int n = 0; n < DSTATE; n++){
        float a[8], b[8];
        #pragma unroll
        for (int r = 0; r < 8; r++) a[r] = Csh[(i0+r)*65 + n];
        #pragma unroll
        for (int c = 0; c < 8; c++) b[c] = Bsh[(j0+c)*65 + n];
        #pragma unroll
        for (int r = 0; r < 8; r++)
            #pragma unroll
            for (int c = 0; c < 8; c++) acc[r][c] += a[r]*b[c];
    }
    float* out = g_sc + (size_t)bc * CHUNKL * CHUNKL;
    #pragma unroll
    for (int r = 0; r < 8; r++)
        #pragma unroll
        for (int c = 0; c < 8; c++)
            out[(i0+r)*CHUNKL + j0 + c] = acc[r][c];
}

// ---------------- y_diag ----------------
__global__ void k_ydiag(){
    int bc = blockIdx.x >> 4, h = blockIdx.x & 15;
    int i  = threadIdx.x;
    int t0 = bc * CHUNKL;
    __shared__ float xsh[CHUNKL*HD];
    __shared__ float ash[CHUNKL], dsh[CHUNKL];
    ash[i] = g_acum[(t0+i)*NH + h];
    dsh[i] = g_dtv [(t0+i)*NH + h];
    for (int idx = i; idx < CHUNKL*HD; idx += CHUNKL)
        xsh[idx] = g_xc[(size_t)(t0 + (idx >> 6))*CONVDIM + h*HD + (idx & 63)];
    __syncthreads();
    float acc[HD];
    #pragma unroll
    for (int p = 0; p < HD; p++) acc[p] = 0.f;
    const float* srow = g_sc + (size_t)bc * CHUNKL * CHUNKL + (size_t)i * CHUNKL;
    float ai = ash[i];
    for (int j = 0; j <= i; j++){
        float m = srow[j] * expf(ai - ash[j]) * dsh[j];
        const float* xr = &xsh[j*HD];
        #pragma unroll
        for (int p = 0; p < HD; p++) acc[p] += m * xr[p];
    }
    float* yrow = g_y + (size_t)(t0+i)*DINNER + h*HD;
    #pragma unroll
    for (int p = 0; p < HD; p++) yrow[p] = acc[p];
}

// ---------------- chunk states ----------------
__global__ void k_state(){
    extern __shared__ float smf[];
    float* xsh = smf;
    float* bsh = smf + CHUNKL*HD;
    __shared__ float wsh[CHUNKL];
    int bc = blockIdx.x >> 4, h = blockIdx.x & 15;
    int t0 = bc * CHUNKL;
    int tid = threadIdx.x;
    for (int idx = tid; idx < CHUNKL*HD; idx += 256){
        int j = idx >> 6, q = idx & 63;
        xsh[idx] = g_xc[(size_t)(t0+j)*CONVDIM + h*HD + q];
        bsh[idx] = g_xc[(size_t)(t0+j)*CONVDIM + DINNER + q];
    }
    if (tid < CHUNKL){
        float alast = g_acum[(t0 + CHUNKL - 1)*NH + h];
        float aj    = g_acum[(t0 + tid)*NH + h];
        wsh[tid] = expf(alast - aj) * g_dtv[(t0 + tid)*NH + h];
    }
    __syncthreads();
    int p  = tid & 63;
    int n0 = (tid >> 6) << 4;
    float acc[16];
    #pragma unroll
    for (int k = 0; k < 16; k++) acc[k] = 0.f;
    for (int j = 0; j < CHUNKL; j++){
        float xw = xsh[j*HD + p] * wsh[j];
        const float* br = &bsh[j*HD + n0];
        #pragma unroll
        for (int k = 0; k < 16; k++) acc[k] += xw * br[k];
    }
    float* so = g_S + (size_t)blockIdx.x * (HD*DSTATE);
    #pragma unroll
    for (int k = 0; k < 16; k++) so[p*DSTATE + n0 + k] = acc[k];
}

// ---------------- scan ----------------
__global__ void k_scan(){
    int b = blockIdx.x >> 4, h = blockIdx.x & 15;
    int tid = threadIdx.x;
    float st[16];
    #pragma unroll
    for (int k = 0; k < 16; k++) st[k] = 0.f;
    for (int c = 0; c < NCH; c++){
        int bch = (b*NCH + c)*NH + h;
        size_t base = (size_t)bch * (HD*DSTATE);
        float dc = g_dec[bch];
        #pragma unroll
        for (int k = 0; k < 16; k++){
            int idx = k*256 + tid;
            g_hs[base + idx] = st[k];
            st[k] = st[k]*dc + g_S[base + idx];
        }
    }
}

// ---------------- y_off + D*xh ----------------
__global__ void k_yoff(const float* __restrict__ Dp){
    int bc = blockIdx.x >> 4, h = blockIdx.x & 15;
    int i  = threadIdx.x;
    int t0 = bc * CHUNKL;
    __shared__ float hsh[HD*DSTATE];
    const float* hbase = g_hs + (size_t)blockIdx.x * (HD*DSTATE);
    for (int idx = i; idx < HD*DSTATE; idx += CHUNKL) hsh[idx] = hbase[idx];
    float creg[DSTATE];
    const float* crow = g_xc + (size_t)(t0+i)*CONVDIM + DINNER + DSTATE;
    #pragma unroll
    for (int n = 0; n < DSTATE; n++) creg[n] = crow[n];
    __syncthreads();
    float ei = expf(g_acum[(t0+i)*NH + h]);
    float Dh = Dp[h];
    const float* xrow = g_xc + (size_t)(t0+i)*CONVDIM + h*HD;
    float* yrow = g_y + (size_t)(t0+i)*DINNER + h*HD;
    for (int p = 0; p < HD; p++){
        float a = 0.f;
        const float* hr = &hsh[p*DSTATE];
        #pragma unroll
        for (int n = 0; n < DSTATE; n++) a += creg[n] * hr[n];
        yrow[p] = yrow[p] + ei * a + Dh * xrow[p];
    }
}

// ---------------- gate: rmsnorm(y*silu(z))*gw -> bf16 hi/lo ----------------
__global__ void k_gate(const float* __restrict__ gw){
    int t = blockIdx.x;
    int tid = threadIdx.x;
    float v[4]; float ss = 0.f;
    #pragma unroll
    for (int k = 0; k < 4; k++){
        int d = k*256 + tid;
        float z = g_zx[(size_t)t*DINPROJ + d];
        float vv = g_y[(size_t)t*DINNER + d] * siluf(z);
        v[k] = vv; ss += vv*vv;
    }
    ss = blockReduceSum(ss);
    float rs = rsqrtf(ss / (float)DINNER + 1e-5f);
    #pragma unroll
    for (int k = 0; k < 4; k++){
        int d = k*256 + tid;
        float o = v[k] * rs * gw[d];
        __nv_bfloat16 hi = __float2bfloat16_rn(o);
        g_ygh[(size_t)t*DINNER + d] = hi;
        g_ygl[(size_t)t*DINNER + d] = __float2bfloat16_rn(o - __bfloat162float(hi));
    }
}

// ---------------- head ----------------
__global__ void k_head(const float* __restrict__ hw, const float* __restrict__ hb,
                       float* __restrict__ out){
    int idx = blockIdx.x * blockDim.x + threadIdx.x;
    if (idx >= NTOK * KOUT) return;
    int t = idx / KOUT, n = idx % KOUT;
    float acc = hb[n];
    const float* xr = g_xn + (size_t)t * DMODEL;
    for (int k = 0; k < DMODEL; k++) acc += xr[k] * hw[k*KOUT + n];
    out[idx] = acc;
}

// ---------------- host orchestration ----------------
extern "C" void kernel_launch(void* const* d_in, const int* in_sizes, int n_in,
                              void* d_out, int out_size){
    const float* x      = (const float*)d_in[0];
    const float* Wembed = (const float*)d_in[1];
    const float* rmsw   = (const float*)d_in[2];
    const float* inw    = (const float*)d_in[3];
    const float* convw  = (const float*)d_in[4];
    const float* convb  = (const float*)d_in[5];
    const float* dtb    = (const float*)d_in[6];
    const float* alog   = (const float*)d_in[7];
    const float* dparam = (const float*)d_in[8];
    const float* gnw    = (const float*)d_in[9];
    const float* outw   = (const float*)d_in[10];
    const float* fnw    = (const float*)d_in[11];
    const float* hw     = (const float*)d_in[12];
    const float* hb     = (const float*)d_in[13];
    float* out = (float*)d_out;

    float *p_h, *p_xn, *p_zx;
    cudaGetSymbolAddress((void**)&p_h,  g_h);
    cudaGetSymbolAddress((void**)&p_xn, g_xn);
    cudaGetSymbolAddress((void**)&p_zx, g_zx);
    __nv_bfloat16 *p_xnh, *p_xnl, *p_ygh, *p_ygl;
    cudaGetSymbolAddress((void**)&p_xnh, g_xnh);
    cudaGetSymbolAddress((void**)&p_xnl, g_xnl);
    cudaGetSymbolAddress((void**)&p_ygh, g_ygh);
    cudaGetSymbolAddress((void**)&p_ygl, g_ygl);
    __nv_bfloat16 *p_wih, *p_wil, *p_woh, *p_wol;
    cudaGetSymbolAddress((void**)&p_wih, g_wih);
    cudaGetSymbolAddress((void**)&p_wil, g_wil);
    cudaGetSymbolAddress((void**)&p_woh, g_woh);
    cudaGetSymbolAddress((void**)&p_wol, g_wol);

    const int SCORES_SMEM = 2*128*65*4;
    const int STATE_SMEM  = 2*CHUNKL*HD*4;
    const int TG_SMEM     = 3*32768;   // 98304
    cudaFuncSetAttribute(k_scores, cudaFuncAttributeMaxDynamicSharedMemorySize, SCORES_SMEM);
    cudaFuncSetAttribute(k_state,  cudaFuncAttributeMaxDynamicSharedMemorySize, STATE_SMEM);
    cudaFuncSetAttribute(k_tgemm,  cudaFuncAttributeMaxDynamicSharedMemorySize, TG_SMEM);

    // weight preprocessing (deterministic, graph-capturable)
    k_prep<<<dim3(DMODEL/32, NPAD_IN/32, NLAYERS), dim3(32,8)>>>(
        inw, p_wih, p_wil, DMODEL, DINPROJ, NPAD_IN);
    k_prep<<<dim3(DINNER/32, DMODEL/32, NLAYERS), dim3(32,8)>>>(
        outw, p_woh, p_wol, DINNER, DMODEL, DMODEL);

    k_embed<<<(NTOK*DMODEL + 255)/256, 256>>>(x, Wembed);

    for (int l = 0; l < NLAYERS; l++){
        k_rmsnorm<<<NTOK, 256>>>(p_h, rmsw + (size_t)l*DMODEL, p_xn, p_xnh, p_xnl, DMODEL);
        k_tgemm<<<dim3(NPAD_IN/128, NTOK/128), 256, TG_SMEM>>>(
            p_xnh, p_xnl,
            p_wih + (size_t)l*NPAD_IN*DMODEL, p_wil + (size_t)l*NPAD_IN*DMODEL,
            p_zx, nullptr, NTOK, DINPROJ, DMODEL);
        k_conv<<<(NTOK*CONVDIM + 255)/256, 256>>>(convw + (size_t)l*CONVDIM*DCONV,
                                                  convb + (size_t)l*CONVDIM);
        k_dt<<<NBC*NH, CHUNKL>>>(dtb + (size_t)l*NH, alog + (size_t)l*NH);
        k_scores<<<NBC, 256, SCORES_SMEM>>>();
        k_ydiag<<<NBC*NH, CHUNKL>>>();
        k_state<<<NBC*NH, 256, STATE_SMEM>>>();
        k_scan<<<BSZ*NH, 256>>>();
        k_yoff<<<NBC*NH, CHUNKL>>>(dparam + (size_t)l*NH);
        k_gate<<<NTOK, 256>>>(gnw + (size_t)l*DINNER);
        k_tgemm<<<dim3(DMODEL/128, NTOK/128), 256, TG_SMEM>>>(
            p_ygh, p_ygl,
            p_woh + (size_t)l*DMODEL*DINNER, p_wol + (size_t)l*DMODEL*DINNER,
            p_h, p_h, NTOK, DMODEL, DINNER);
    }

    k_rmsnorm<<<NTOK, 256>>>(p_h, fnw, p_xn, p_xnh, p_xnl, DMODEL);
    k_head<<<(NTOK*KOUT + 255)/256, 256>>>(hw, hb, out);
}

// round 5
// speedup vs baseline: 1.6669x; 1.0996x over previous
#include <cuda_runtime.h>
#include <cuda_bf16.h>
#include <math.h>
#include <stdint.h>

// ---------------- problem constants ----------------
#define BSZ     2
#define SEQL    2048
#define NTOK    (BSZ*SEQL)        // 4096
#define DMODEL  512
#define DINNER  1024
#define NH      16
#define HD      64
#define DSTATE  64
#define DCONV   4
#define CONVDIM 1152              // DINNER + 2*DSTATE
#define DINPROJ 2192              // 2*DINNER + 2*DSTATE + NH
#define NPAD_IN 2304              // DINPROJ padded to 128
#define NLAYERS 12
#define CHUNKL  128
#define NCH     16                // chunks per batch
#define NBC     (BSZ*NCH)         // 32
#define KOUT    30                // KLEN*3

// ---------------- scratch (static device globals; allocation-free) ----------
__device__ float g_h   [NTOK*DMODEL];
__device__ float g_xn  [NTOK*DMODEL];
__device__ float g_zx  [NTOK*DINPROJ];
__device__ float g_xc  [NTOK*CONVDIM];
__device__ float g_dtv [NTOK*NH];
__device__ float g_acum[NTOK*NH];
__device__ float g_dec [NBC*NH];
__device__ float g_sc  [NBC*CHUNKL*CHUNKL];
__device__ float g_y   [NTOK*DINNER];
__device__ float g_S   [NBC*NH*HD*DSTATE];
__device__ float g_hs  [NBC*NH*HD*DSTATE];
// bf16 hi/lo activations
__device__ __nv_bfloat16 g_xnh[NTOK*DMODEL];
__device__ __nv_bfloat16 g_xnl[NTOK*DMODEL];
__device__ __nv_bfloat16 g_ygh[NTOK*DINNER];
__device__ __nv_bfloat16 g_ygl[NTOK*DINNER];
// bf16 hi/lo transposed weights [layer][Npad][K]
__device__ __nv_bfloat16 g_wih[NLAYERS*NPAD_IN*DMODEL];
__device__ __nv_bfloat16 g_wil[NLAYERS*NPAD_IN*DMODEL];
__device__ __nv_bfloat16 g_woh[NLAYERS*DMODEL*DINNER];
__device__ __nv_bfloat16 g_wol[NLAYERS*DMODEL*DINNER];

// ---------------- small helpers ----------------
__device__ __forceinline__ uint32_t s2u(const void* p){
    uint32_t a;
    asm("{ .reg .u64 t; cvta.to.shared.u64 t, %1; cvt.u32.u64 %0, t; }" : "=r"(a) : "l"(p));
    return a;
}
__device__ __forceinline__ void ldsm4(uint32_t* r, uint32_t a){
    asm volatile("ldmatrix.sync.aligned.m8n8.x4.shared.b16 {%0,%1,%2,%3}, [%4];"
        : "=r"(r[0]), "=r"(r[1]), "=r"(r[2]), "=r"(r[3]) : "r"(a));
}
__device__ __forceinline__ void mma16816(float* d, const uint32_t* a, uint32_t b0, uint32_t b1){
    asm volatile("mma.sync.aligned.m16n8k16.row.col.f32.bf16.bf16.f32 "
        "{%0,%1,%2,%3}, {%4,%5,%6,%7}, {%8,%9}, {%0,%1,%2,%3};"
        : "+f"(d[0]), "+f"(d[1]), "+f"(d[2]), "+f"(d[3])
        : "r"(a[0]), "r"(a[1]), "r"(a[2]), "r"(a[3]), "r"(b0), "r"(b1));
}
__device__ __forceinline__ void cpasync16(uint32_t s, const void* g){
    uint64_t ga;
    asm("cvta.to.global.u64 %0, %1;" : "=l"(ga) : "l"(g));
    asm volatile("cp.async.cg.shared.global [%0], [%1], 16;" :: "r"(s), "l"(ga));
}
__device__ __forceinline__ void cpcommit(){ asm volatile("cp.async.commit_group;"); }
__device__ __forceinline__ void cpwait1(){ asm volatile("cp.async.wait_group 1;"); }

__device__ __forceinline__ float softplusf(float x){
    return (x > 20.f) ? x : log1pf(expf(x));
}
__device__ __forceinline__ float siluf(float x){
    return x / (1.f + expf(-x));
}
__device__ __forceinline__ float blockReduceSum(float v){
    __shared__ float sh[32];
    #pragma unroll
    for (int o = 16; o; o >>= 1) v += __shfl_xor_sync(0xffffffffu, v, o);
    int w = threadIdx.x >> 5;
    if ((threadIdx.x & 31) == 0) sh[w] = v;
    __syncthreads();
    int nw = blockDim.x >> 5;
    float r = (threadIdx.x < nw) ? sh[threadIdx.x] : 0.f;
    if (w == 0){
        #pragma unroll
        for (int o = 16; o; o >>= 1) r += __shfl_xor_sync(0xffffffffu, r, o);
        if (threadIdx.x == 0) sh[0] = r;
    }
    __syncthreads();
    return sh[0];
}

// ---------------- weight prep: transpose + bf16 hi/lo split ----------------
__global__ void k_prep(const float* __restrict__ W, __nv_bfloat16* __restrict__ Whi,
                       __nv_bfloat16* __restrict__ Wlo, int K, int N, int Npad){
    int l = blockIdx.z;
    W   += (size_t)l * K * N;
    Whi += (size_t)l * Npad * K;
    Wlo += (size_t)l * Npad * K;
    __shared__ float t[32][33];
    int k0 = blockIdx.x * 32, n0 = blockIdx.y * 32;
    int tx = threadIdx.x, ty = threadIdx.y;
    for (int i = ty; i < 32; i += 8){
        float v = 0.f;
        if (n0 + tx < N) v = W[(size_t)(k0 + i) * N + n0 + tx];
        t[i][tx] = v;
    }
    __syncthreads();
    for (int i = ty; i < 32; i += 8){
        float v = t[tx][i];   // W[k0+tx][n0+i]
        __nv_bfloat16 hi = __float2bfloat16_rn(v);
        float lo = v - __bfloat162float(hi);
        Whi[(size_t)(n0 + i) * K + k0 + tx] = hi;
        Wlo[(size_t)(n0 + i) * K + k0 + tx] = __float2bfloat16_rn(lo);
    }
}

// ---------------- mma.sync bf16x3 GEMM, 512 threads, 3-stage pipeline --------
// C[M][N](+R) = (Ah+Al)[M][K] @ (Bh+Bl)^T, B stored [Npad][K].
// CTA 128x128 tile, 16 warps (each 32x32), k-chunk 32. One sync per iter.
// SMEM per buffer: A 128 rows x 128B at +0, B at +16384. Buffers stride 32768.
__global__ void __launch_bounds__(512, 1)
k_tgemm(const __nv_bfloat16* __restrict__ Ah, const __nv_bfloat16* __restrict__ Al,
        const __nv_bfloat16* __restrict__ Bh, const __nv_bfloat16* __restrict__ Bl,
        float* __restrict__ C, const float* __restrict__ R,
        int M, int N, int K)
{
    extern __shared__ char smc[];
    uint32_t sb = s2u(smc);
    int tid  = threadIdx.x;
    int lane = tid & 31, w = tid >> 5;
    int wm = w & 3, wn = w >> 2;
    int m0 = blockIdx.y * 128, n0 = blockIdx.x * 128;

    // loader: rp = tid>>1 (0..255): row = rp>>1, part = rp&1; ch2 = tid&1 -> 2 chunks
    int lrow  = tid >> 2;           // 0..127
    int lpart = (tid >> 1) & 1;     // 0 hi, 1 lo
    int lch   = (tid & 1) * 2;      // chunk base 0 or 2
    const __nv_bfloat16* gA = (lpart ? Al : Ah) + (size_t)(m0 + lrow) * K;
    const __nv_bfloat16* gB = (lpart ? Bl : Bh) + (size_t)(n0 + lrow) * K;
    uint32_t sArow = sb + (uint32_t)lrow * 128;
    uint32_t sBrow = sb + 16384u + (uint32_t)lrow * 128;
    uint32_t lsw[2];
    #pragma unroll
    for (int c = 0; c < 2; c++)
        lsw[c] = (uint32_t)(((lpart * 4 + lch + c) ^ (lrow & 7)) * 16);

    float acc[2][4][4];
    #pragma unroll
    for (int mt = 0; mt < 2; mt++)
        #pragma unroll
        for (int nt = 0; nt < 4; nt++)
            #pragma unroll
            for (int e = 0; e < 4; e++) acc[mt][nt][e] = 0.f;

    uint32_t aoff = sb + (uint32_t)((wm * 32 + (lane & 15)) * 128);
    uint32_t boff = sb + 16384u + (uint32_t)((wn * 32 + (lane & 15)) * 128);
    uint32_t ct[2][2]; // [part][kh]
    #pragma unroll
    for (int part = 0; part < 2; part++)
        #pragma unroll
        for (int kh = 0; kh < 2; kh++)
            ct[part][kh] = (uint32_t)((((part * 4 + 2 * kh + (lane >> 4))) ^ (lane & 7)) * 16);

    int nit = K / 32;
    // prologue: chunk 0 -> buf0, chunk 1 -> buf1
    {
        #pragma unroll
        for (int c = 0; c < 2; c++) cpasync16(sArow + lsw[c], gA + (lch + c) * 8);
        #pragma unroll
        for (int c = 0; c < 2; c++) cpasync16(sBrow + lsw[c], gB + (lch + c) * 8);
        cpcommit();
        if (nit > 1){
            #pragma unroll
            for (int c = 0; c < 2; c++) cpasync16(sArow + 32768u + lsw[c], gA + 32 + (lch + c) * 8);
            #pragma unroll
            for (int c = 0; c < 2; c++) cpasync16(sBrow + 32768u + lsw[c], gB + 32 + (lch + c) * 8);
        }
        cpcommit();
    }

    int cur = 0, nxt = 2;
    for (int it = 0; it < nit; it++){
        cpwait1();
        __syncthreads();
        if (it + 2 < nit){
            uint32_t bo = (uint32_t)nxt * 32768u;
            int k0 = (it + 2) * 32;
            #pragma unroll
            for (int c = 0; c < 2; c++) cpasync16(sArow + bo + lsw[c], gA + k0 + (lch + c) * 8);
            #pragma unroll
            for (int c = 0; c < 2; c++) cpasync16(sBrow + bo + lsw[c], gB + k0 + (lch + c) * 8);
        }
        cpcommit();

        uint32_t bufo = (uint32_t)cur * 32768u;
        #pragma unroll
        for (int kh = 0; kh < 2; kh++){
            uint32_t ah[2][4], al[2][4], bh[2][4], bl[2][4];
            #pragma unroll
            for (int mt = 0; mt < 2; mt++){
                uint32_t base = aoff + bufo + (uint32_t)(mt * 2048);
                ldsm4(ah[mt], base + ct[0][kh]);
                ldsm4(al[mt], base + ct[1][kh]);
            }
            #pragma unroll
            for (int g = 0; g < 2; g++){
                uint32_t base = boff + bufo + (uint32_t)(g * 2048);
                ldsm4(bh[g], base + ct[0][kh]);
                ldsm4(bl[g], base + ct[1][kh]);
            }
            #pragma unroll
            for (int mt = 0; mt < 2; mt++)
                #pragma unroll
                for (int nt = 0; nt < 4; nt++){
                    int g = nt >> 1, s = nt & 1;
                    mma16816(acc[mt][nt], ah[mt], bh[g][s], bh[g][s + 2]);
                    mma16816(acc[mt][nt], ah[mt], bl[g][s], bl[g][s + 2]);
                    mma16816(acc[mt][nt], al[mt], bh[g][s], bh[g][s + 2]);
                }
        }
        if (++cur == 3) cur = 0;
        if (++nxt == 3) nxt = 0;
    }

    // epilogue
    #pragma unroll
    for (int mt = 0; mt < 2; mt++){
        int m = m0 + wm * 32 + mt * 16 + (lane >> 2);
        #pragma unroll
        for (int nt = 0; nt < 4; nt++){
            int col = n0 + wn * 32 + nt * 8 + (lane & 3) * 2;
            if (col < N){
                size_t i0 = (size_t)m * N + col;
                size_t i1 = (size_t)(m + 8) * N + col;
                float2 v0 = make_float2(acc[mt][nt][0], acc[mt][nt][1]);
                float2 v1 = make_float2(acc[mt][nt][2], acc[mt][nt][3]);
                if (R){
                    float2 r0 = *(const float2*)(R + i0);
                    float2 r1 = *(const float2*)(R + i1);
                    v0.x += r0.x; v0.y += r0.y;
                    v1.x += r1.x; v1.y += r1.y;
                }
                *(float2*)(C + i0) = v0;
                *(float2*)(C + i1) = v1;
            }
        }
    }
}

// ---------------- embedding: x@W_embed + nerf_pe ----------------
__global__ void k_embed(const float* __restrict__ x, const float* __restrict__ W){
    int idx = blockIdx.x * blockDim.x + threadIdx.x;
    if (idx >= NTOK * DMODEL) return;
    int t = idx / DMODEL, d = idx % DMODEL;
    float x0 = x[t*3+0]; if (x0 == -100.f) x0 = 0.f;
    float x1 = x[t*3+1]; if (x1 == -100.f) x1 = 0.f;
    float x2 = x[t*3+2]; if (x2 == -100.f) x2 = 0.f;
    float acc = x0 * W[0*DMODEL + d] + x1 * W[1*DMODEL + d] + x2 * W[2*DMODEL + d];
    if (d < 510){
        int c = d / 170, r = d % 170;
        float xv = (c == 0) ? x0 : ((c == 1) ? x1 : x2);
        float pe;
        if (r < 85) pe = sinf(xv * exp2f((float)r));
        else        pe = cosf(xv * exp2f((float)(r - 85)));
        acc += pe;
    }
    g_h[idx] = acc;
}

// ---------------- rmsnorm: fp32 out + bf16 hi/lo out ----------------
__global__ void k_rmsnorm(const float* __restrict__ x, const float* __restrict__ w,
                          float* __restrict__ o, __nv_bfloat16* __restrict__ oh,
                          __nv_bfloat16* __restrict__ ol, int D){
    int t = blockIdx.x;
    const float* xr = x + (size_t)t * D;
    float ss = 0.f;
    for (int d = threadIdx.x; d < D; d += blockDim.x){
        float v = xr[d];
        ss += v * v;
    }
    ss = blockReduceSum(ss);
    float rs = rsqrtf(ss / (float)D + 1e-5f);
    for (int d = threadIdx.x; d < D; d += blockDim.x){
        float v = xr[d] * rs * w[d];
        o[(size_t)t * D + d] = v;
        __nv_bfloat16 hi = __float2bfloat16_rn(v);
        oh[(size_t)t * D + d] = hi;
        ol[(size_t)t * D + d] = __float2bfloat16_rn(v - __bfloat162float(hi));
    }
}

// ---------------- causal depthwise conv + silu ----------------
__global__ void k_conv(const float* __restrict__ cw, const float* __restrict__ cb){
    int idx = blockIdx.x * blockDim.x + threadIdx.x;
    if (idx >= NTOK * CONVDIM) return;
    int t = idx / CONVDIM, ch = idx % CONVDIM;
    int l = t % SEQL;
    float acc = cb[ch];
    #pragma unroll
    for (int k = 0; k < DCONV; k++){
        int l2 = l + k - (DCONV - 1);
        if (l2 >= 0)
            acc += g_zx[(size_t)(t + l2 - l) * DINPROJ + DINNER + ch] * cw[ch*DCONV + k];
    }
    g_xc[idx] = siluf(acc);
}

// ---------------- dt prep ----------------
__global__ void k_dt(const float* __restrict__ dtb, const float* __restrict__ Alog){
    int bc = blockIdx.x >> 4;
    int h  = blockIdx.x & 15;
    int i  = threadIdx.x;              // 128
    int t  = bc * CHUNKL + i;
    float d = softplusf(g_zx[(size_t)t * DINPROJ + 2176 + h] + dtb[h]);
    float A = -expf(Alog[h]);
    __shared__ float sh[CHUNKL];
    sh[i] = d * A;
    __syncthreads();
    #pragma unroll
    for (int off = 1; off < CHUNKL; off <<= 1){
        float v = (i >= off) ? sh[i - off] : 0.f;
        __syncthreads();
        sh[i] += v;
        __syncthreads();
    }
    g_dtv [t*NH + h] = d;
    g_acum[t*NH + h] = sh[i];
    if (i == CHUNKL - 1) g_dec[blockIdx.x] = expf(sh[i]);
}

// ---------------- scores ----------------
__global__ void k_scores(){
    extern __shared__ float smf[];
    float* Csh = smf;
    float* Bsh = smf + 128*65;
    int bc = blockIdx.x;
    int t0 = bc * CHUNKL;
    int tid = threadIdx.x;
    for (int idx = tid; idx < CHUNKL*DSTATE; idx += 256){
        int j = idx >> 6, n = idx & 63;
        Csh[j*65 + n] = g_xc[(size_t)(t0+j)*CONVDIM + DINNER + DSTATE + n];
        Bsh[j*65 + n] = g_xc[(size_t)(t0+j)*CONVDIM + DINNER + n];
    }
    __syncthreads();
    int i0 = (tid >> 4) * 8;
    int j0 = (tid & 15) * 8;
    float acc[8][8];
    #pragma unroll
    for (int r = 0; r < 8; r++)
        #pragma unroll
        for (int c = 0; c < 8; c++) acc[r][c] = 0.f;
    for (int n = 0; n < DSTATE; n++){
        float a[8], b[8];
        #pragma unroll
        for (int r = 0; r < 8; r++) a[r] = Csh[(i0+r)*65 + n];
        #pragma unroll
        for (int c = 0; c < 8; c++) b[c] = Bsh[(j0+c)*65 + n];
        #pragma unroll
        for (int r = 0; r < 8; r++)
            #pragma unroll
            for (int c = 0; c < 8; c++) acc[r][c] += a[r]*b[c];
    }
    float* out = g_sc + (size_t)bc * CHUNKL * CHUNKL;
    #pragma unroll
    for (int r = 0; r < 8; r++)
        #pragma unroll
        for (int c = 0; c < 8; c++)
            out[(i0+r)*CHUNKL + j0 + c] = acc[r][c];
}

// ---------------- y_diag ----------------
__global__ void k_ydiag(){
    int bc = blockIdx.x >> 4, h = blockIdx.x & 15;
    int i  = threadIdx.x;
    int t0 = bc * CHUNKL;
    __shared__ float xsh[CHUNKL*HD];
    __shared__ float ash[CHUNKL], dsh[CHUNKL];
    ash[i] = g_acum[(t0+i)*NH + h];
    dsh[i] = g_dtv [(t0+i)*NH + h];
    for (int idx = i; idx < CHUNKL*HD; idx += CHUNKL)
        xsh[idx] = g_xc[(size_t)(t0 + (idx >> 6))*CONVDIM + h*HD + (idx & 63)];
    __syncthreads();
    float acc[HD];
    #pragma unroll
    for (int p = 0; p < HD; p++) acc[p] = 0.f;
    const float* srow = g_sc + (size_t)bc * CHUNKL * CHUNKL + (size_t)i * CHUNKL;
    float ai = ash[i];
    for (int j = 0; j <= i; j++){
        float m = srow[j] * expf(ai - ash[j]) * dsh[j];
        const float* xr = &xsh[j*HD];
        #pragma unroll
        for (int p = 0; p < HD; p++) acc[p] += m * xr[p];
    }
    float* yrow = g_y + (size_t)(t0+i)*DINNER + h*HD;
    #pragma unroll
    for (int p = 0; p < HD; p++) yrow[p] = acc[p];
}

// ---------------- chunk states ----------------
__global__ void k_state(){
    extern __shared__ float smf[];
    float* xsh = smf;
    float* bsh = smf + CHUNKL*HD;
    __shared__ float wsh[CHUNKL];
    int bc = blockIdx.x >> 4, h = blockIdx.x & 15;
    int t0 = bc * CHUNKL;
    int tid = threadIdx.x;
    for (int idx = tid; idx < CHUNKL*HD; idx += 256){
        int j = idx >> 6, q = idx & 63;
        xsh[idx] = g_xc[(size_t)(t0+j)*CONVDIM + h*HD + q];
        bsh[idx] = g_xc[(size_t)(t0+j)*CONVDIM + DINNER + q];
    }
    if (tid < CHUNKL){
        float alast = g_acum[(t0 + CHUNKL - 1)*NH + h];
        float aj    = g_acum[(t0 + tid)*NH + h];
        wsh[tid] = expf(alast - aj) * g_dtv[(t0 + tid)*NH + h];
    }
    __syncthreads();
    int p  = tid & 63;
    int n0 = (tid >> 6) << 4;
    float acc[16];
    #pragma unroll
    for (int k = 0; k < 16; k++) acc[k] = 0.f;
    for (int j = 0; j < CHUNKL; j++){
        float xw = xsh[j*HD + p] * wsh[j];
        const float* br = &bsh[j*HD + n0];
        #pragma unroll
        for (int k = 0; k < 16; k++) acc[k] += xw * br[k];
    }
    float* so = g_S + (size_t)blockIdx.x * (HD*DSTATE);
    #pragma unroll
    for (int k = 0; k < 16; k++) so[p*DSTATE + n0 + k] = acc[k];
}

// ---------------- scan ----------------
__global__ void k_scan(){
    int b = blockIdx.x >> 4, h = blockIdx.x & 15;
    int tid = threadIdx.x;
    float st[16];
    #pragma unroll
    for (int k = 0; k < 16; k++) st[k] = 0.f;
    for (int c = 0; c < NCH; c++){
        int bch = (b*NCH + c)*NH + h;
        size_t base = (size_t)bch * (HD*DSTATE);
        float dc = g_dec[bch];
        #pragma unroll
        for (int k = 0; k < 16; k++){
            int idx = k*256 + tid;
            g_hs[base + idx] = st[k];
            st[k] = st[k]*dc + g_S[base + idx];
        }
    }
}

// ---------------- y_off + D*xh ----------------
__global__ void k_yoff(const float* __restrict__ Dp){
    int bc = blockIdx.x >> 4, h = blockIdx.x & 15;
    int i  = threadIdx.x;
    int t0 = bc * CHUNKL;
    __shared__ float hsh[HD*DSTATE];
    const float* hbase = g_hs + (size_t)blockIdx.x * (HD*DSTATE);
    for (int idx = i; idx < HD*DSTATE; idx += CHUNKL) hsh[idx] = hbase[idx];
    float creg[DSTATE];
    const float* crow = g_xc + (size_t)(t0+i)*CONVDIM + DINNER + DSTATE;
    #pragma unroll
    for (int n = 0; n < DSTATE; n++) creg[n] = crow[n];
    __syncthreads();
    float ei = expf(g_acum[(t0+i)*NH + h]);
    float Dh = Dp[h];
    const float* xrow = g_xc + (size_t)(t0+i)*CONVDIM + h*HD;
    float* yrow = g_y + (size_t)(t0+i)*DINNER + h*HD;
    for (int p = 0; p < HD; p++){
        float a = 0.f;
        const float* hr = &hsh[p*DSTATE];
        #pragma unroll
        for (int n = 0; n < DSTATE; n++) a += creg[n] * hr[n];
        yrow[p] = yrow[p] + ei * a + Dh * xrow[p];
    }
}

// ---------------- gate: rmsnorm(y*silu(z))*gw -> bf16 hi/lo ----------------
__global__ void k_gate(const float* __restrict__ gw){
    int t = blockIdx.x;
    int tid = threadIdx.x;
    float v[4]; float ss = 0.f;
    #pragma unroll
    for (int k = 0; k < 4; k++){
        int d = k*256 + tid;
        float z = g_zx[(size_t)t*DINPROJ + d];
        float vv = g_y[(size_t)t*DINNER + d] * siluf(z);
        v[k] = vv; ss += vv*vv;
    }
    ss = blockReduceSum(ss);
    float rs = rsqrtf(ss / (float)DINNER + 1e-5f);
    #pragma unroll
    for (int k = 0; k < 4; k++){
        int d = k*256 + tid;
        float o = v[k] * rs * gw[d];
        __nv_bfloat16 hi = __float2bfloat16_rn(o);
        g_ygh[(size_t)t*DINNER + d] = hi;
        g_ygl[(size_t)t*DINNER + d] = __float2bfloat16_rn(o - __bfloat162float(hi));
    }
}

// ---------------- head ----------------
__global__ void k_head(const float* __restrict__ hw, const float* __restrict__ hb,
                       float* __restrict__ out){
    int idx = blockIdx.x * blockDim.x + threadIdx.x;
    if (idx >= NTOK * KOUT) return;
    int t = idx / KOUT, n = idx % KOUT;
    float acc = hb[n];
    const float* xr = g_xn + (size_t)t * DMODEL;
    for (int k = 0; k < DMODEL; k++) acc += xr[k] * hw[k*KOUT + n];
    out[idx] = acc;
}

// ---------------- host orchestration ----------------
extern "C" void kernel_launch(void* const* d_in, const int* in_sizes, int n_in,
                              void* d_out, int out_size){
    const float* x      = (const float*)d_in[0];
    const float* Wembed = (const float*)d_in[1];
    const float* rmsw   = (const float*)d_in[2];
    const float* inw    = (const float*)d_in[3];
    const float* convw  = (const float*)d_in[4];
    const float* convb  = (const float*)d_in[5];
    const float* dtb    = (const float*)d_in[6];
    const float* alog   = (const float*)d_in[7];
    const float* dparam = (const float*)d_in[8];
    const float* gnw    = (const float*)d_in[9];
    const float* outw   = (const float*)d_in[10];
    const float* fnw    = (const float*)d_in[11];
    const float* hw     = (const float*)d_in[12];
    const float* hb     = (const float*)d_in[13];
    float* out = (float*)d_out;

    float *p_h, *p_xn, *p_zx;
    cudaGetSymbolAddress((void**)&p_h,  g_h);
    cudaGetSymbolAddress((void**)&p_xn, g_xn);
    cudaGetSymbolAddress((void**)&p_zx, g_zx);
    __nv_bfloat16 *p_xnh, *p_xnl, *p_ygh, *p_ygl;
    cudaGetSymbolAddress((void**)&p_xnh, g_xnh);
    cudaGetSymbolAddress((void**)&p_xnl, g_xnl);
    cudaGetSymbolAddress((void**)&p_ygh, g_ygh);
    cudaGetSymbolAddress((void**)&p_ygl, g_ygl);
    __nv_bfloat16 *p_wih, *p_wil, *p_woh, *p_wol;
    cudaGetSymbolAddress((void**)&p_wih, g_wih);
    cudaGetSymbolAddress((void**)&p_wil, g_wil);
    cudaGetSymbolAddress((void**)&p_woh, g_woh);
    cudaGetSymbolAddress((void**)&p_wol, g_wol);

    const int SCORES_SMEM = 2*128*65*4;
    const int STATE_SMEM  = 2*CHUNKL*HD*4;
    const int TG_SMEM     = 3*32768;   // 98304
    cudaFuncSetAttribute(k_scores, cudaFuncAttributeMaxDynamicSharedMemorySize, SCORES_SMEM);
    cudaFuncSetAttribute(k_state,  cudaFuncAttributeMaxDynamicSharedMemorySize, STATE_SMEM);
    cudaFuncSetAttribute(k_tgemm,  cudaFuncAttributeMaxDynamicSharedMemorySize, TG_SMEM);

    // weight preprocessing (deterministic, graph-capturable)
    k_prep<<<dim3(DMODEL/32, NPAD_IN/32, NLAYERS), dim3(32,8)>>>(
        inw, p_wih, p_wil, DMODEL, DINPROJ, NPAD_IN);
    k_prep<<<dim3(DINNER/32, DMODEL/32, NLAYERS), dim3(32,8)>>>(
        outw, p_woh, p_wol, DINNER, DMODEL, DMODEL);

    k_embed<<<(NTOK*DMODEL + 255)/256, 256>>>(x, Wembed);

    for (int l = 0; l < NLAYERS; l++){
        k_rmsnorm<<<NTOK, 256>>>(p_h, rmsw + (size_t)l*DMODEL, p_xn, p_xnh, p_xnl, DMODEL);
        k_tgemm<<<dim3(NPAD_IN/128, NTOK/128), 512, TG_SMEM>>>(
            p_xnh, p_xnl,
            p_wih + (size_t)l*NPAD_IN*DMODEL, p_wil + (size_t)l*NPAD_IN*DMODEL,
            p_zx, nullptr, NTOK, DINPROJ, DMODEL);
        k_conv<<<(NTOK*CONVDIM + 255)/256, 256>>>(convw + (size_t)l*CONVDIM*DCONV,
                                                  convb + (size_t)l*CONVDIM);
        k_dt<<<NBC*NH, CHUNKL>>>(dtb + (size_t)l*NH, alog + (size_t)l*NH);
        k_scores<<<NBC, 256, SCORES_SMEM>>>();
        k_ydiag<<<NBC*NH, CHUNKL>>>();
        k_state<<<NBC*NH, 256, STATE_SMEM>>>();
        k_scan<<<BSZ*NH, 256>>>();
        k_yoff<<<NBC*NH, CHUNKL>>>(dparam + (size_t)l*NH);
        k_gate<<<NTOK, 256>>>(gnw + (size_t)l*DINNER);
        k_tgemm<<<dim3(DMODEL/128, NTOK/128), 512, TG_SMEM>>>(
            p_ygh, p_ygl,
            p_woh + (size_t)l*DMODEL*DINNER, p_wol + (size_t)l*DMODEL*DINNER,
            p_h, p_h, NTOK, DMODEL, DINNER);
    }

    k_rmsnorm<<<NTOK, 256>>>(p_h, fnw, p_xn, p_xnh, p_xnl, DMODEL);
    k_head<<<(NTOK*KOUT + 255)/256, 256>>>(hw, hb, out);
}

// round 6
// speedup vs baseline: 1.7645x; 1.0586x over previous
#include <cuda_runtime.h>
#include <cuda_bf16.h>
#include <math.h>
#include <stdint.h>

// ---------------- problem constants ----------------
#define BSZ     2
#define SEQL    2048
#define NTOK    (BSZ*SEQL)        // 4096
#define DMODEL  512
#define DINNER  1024
#define NH      16
#define HD      64
#define DSTATE  64
#define DCONV   4
#define CONVDIM 1152
#define DINPROJ 2192
#define NPAD_IN 2304
#define NLAYERS 12
#define CHUNKL  128
#define NCH     16
#define NBC     (BSZ*NCH)         // 32
#define KOUT    30
#define AWIN    35.0f             // exp window cutoff

// ---------------- scratch ----------
__device__ float g_h   [NTOK*DMODEL];
__device__ float g_xn  [NTOK*DMODEL];
__device__ float g_zx  [NTOK*DINPROJ];
__device__ float g_xc  [NTOK*CONVDIM];
__device__ float g_dtv [NTOK*NH];
__device__ float g_acum[NTOK*NH];
__device__ float g_dec [NBC*NH];
__device__ float g_sc  [NBC*CHUNKL*CHUNKL];
__device__ float g_y   [NTOK*DINNER];
__device__ float g_S   [NBC*NH*HD*DSTATE];
__device__ float g_hs  [NBC*NH*HD*DSTATE];
__device__ __nv_bfloat16 g_xnh[NTOK*DMODEL];
__device__ __nv_bfloat16 g_xnl[NTOK*DMODEL];
__device__ __nv_bfloat16 g_ygh[NTOK*DINNER];
__device__ __nv_bfloat16 g_ygl[NTOK*DINNER];
__device__ __nv_bfloat16 g_wih[NLAYERS*NPAD_IN*DMODEL];
__device__ __nv_bfloat16 g_wil[NLAYERS*NPAD_IN*DMODEL];
__device__ __nv_bfloat16 g_woh[NLAYERS*DMODEL*DINNER];
__device__ __nv_bfloat16 g_wol[NLAYERS*DMODEL*DINNER];

// ---------------- helpers ----------------
__device__ __forceinline__ uint32_t s2u(const void* p){
    uint32_t a;
    asm("{ .reg .u64 t; cvta.to.shared.u64 t, %1; cvt.u32.u64 %0, t; }" : "=r"(a) : "l"(p));
    return a;
}
__device__ __forceinline__ void ldsm4(uint32_t* r, uint32_t a){
    asm volatile("ldmatrix.sync.aligned.m8n8.x4.shared.b16 {%0,%1,%2,%3}, [%4];"
        : "=r"(r[0]), "=r"(r[1]), "=r"(r[2]), "=r"(r[3]) : "r"(a));
}
__device__ __forceinline__ void mma16816(float* d, const uint32_t* a, uint32_t b0, uint32_t b1){
    asm volatile("mma.sync.aligned.m16n8k16.row.col.f32.bf16.bf16.f32 "
        "{%0,%1,%2,%3}, {%4,%5,%6,%7}, {%8,%9}, {%0,%1,%2,%3};"
        : "+f"(d[0]), "+f"(d[1]), "+f"(d[2]), "+f"(d[3])
        : "r"(a[0]), "r"(a[1]), "r"(a[2]), "r"(a[3]), "r"(b0), "r"(b1));
}
__device__ __forceinline__ void cpasync16(uint32_t s, const void* g){
    uint64_t ga;
    asm("cvta.to.global.u64 %0, %1;" : "=l"(ga) : "l"(g));
    asm volatile("cp.async.cg.shared.global [%0], [%1], 16;" :: "r"(s), "l"(ga));
}
__device__ __forceinline__ void cpcommit(){ asm volatile("cp.async.commit_group;"); }
__device__ __forceinline__ void cpwait1(){ asm volatile("cp.async.wait_group 1;"); }

__device__ __forceinline__ float softplusf(float x){
    return (x > 20.f) ? x : log1pf(expf(x));
}
__device__ __forceinline__ float siluf(float x){
    return x / (1.f + expf(-x));
}
__device__ __forceinline__ float blockReduceSum(float v){
    __shared__ float sh[32];
    #pragma unroll
    for (int o = 16; o; o >>= 1) v += __shfl_xor_sync(0xffffffffu, v, o);
    int w = threadIdx.x >> 5;
    if ((threadIdx.x & 31) == 0) sh[w] = v;
    __syncthreads();
    int nw = blockDim.x >> 5;
    float r = (threadIdx.x < nw) ? sh[threadIdx.x] : 0.f;
    if (w == 0){
        #pragma unroll
        for (int o = 16; o; o >>= 1) r += __shfl_xor_sync(0xffffffffu, r, o);
        if (threadIdx.x == 0) sh[0] = r;
    }
    __syncthreads();
    return sh[0];
}

// ---------------- weight prep ----------------
__global__ void k_prep(const float* __restrict__ W, __nv_bfloat16* __restrict__ Whi,
                       __nv_bfloat16* __restrict__ Wlo, int K, int N, int Npad){
    int l = blockIdx.z;
    W   += (size_t)l * K * N;
    Whi += (size_t)l * Npad * K;
    Wlo += (size_t)l * Npad * K;
    __shared__ float t[32][33];
    int k0 = blockIdx.x * 32, n0 = blockIdx.y * 32;
    int tx = threadIdx.x, ty = threadIdx.y;
    for (int i = ty; i < 32; i += 8){
        float v = 0.f;
        if (n0 + tx < N) v = W[(size_t)(k0 + i) * N + n0 + tx];
        t[i][tx] = v;
    }
    __syncthreads();
    for (int i = ty; i < 32; i += 8){
        float v = t[tx][i];
        __nv_bfloat16 hi = __float2bfloat16_rn(v);
        float lo = v - __bfloat162float(hi);
        Whi[(size_t)(n0 + i) * K + k0 + tx] = hi;
        Wlo[(size_t)(n0 + i) * K + k0 + tx] = __float2bfloat16_rn(lo);
    }
}

// ---------------- mma.sync bf16x3 GEMM, 512 thr, k-chunk 64, 3 stages -------
// Buffer (64KB): AHI 0, ALO 16384, BHI 32768, BLO 49152. Stride 65536.
__global__ void __launch_bounds__(512, 1)
k_tgemm(const __nv_bfloat16* __restrict__ Ah, const __nv_bfloat16* __restrict__ Al,
        const __nv_bfloat16* __restrict__ Bh, const __nv_bfloat16* __restrict__ Bl,
        float* __restrict__ C, const float* __restrict__ R,
        int M, int N, int K)
{
    extern __shared__ char smc[];
    uint32_t sb = s2u(smc);
    int tid  = threadIdx.x;
    int lane = tid & 31, w = tid >> 5;
    int wm = w & 3, wn = w >> 2;
    int m0 = blockIdx.y * 128, n0 = blockIdx.x * 128;

    // loader: 4 A segments + 4 B segments per thread
    const __nv_bfloat16* gA[4];
    const __nv_bfloat16* gB[4];
    uint32_t soA[4], soB[4];
    #pragma unroll
    for (int c = 0; c < 4; c++){
        int q = tid * 4 + c;             // 0..2047
        int part = q >> 10, row = (q >> 3) & 127, seg = q & 7;
        uint32_t sw = (uint32_t)((seg ^ (row & 7)) * 16);
        gA[c] = (part ? Al : Ah) + (size_t)(m0 + row) * K + seg * 8;
        gB[c] = (part ? Bl : Bh) + (size_t)(n0 + row) * K + seg * 8;
        soA[c] = (uint32_t)(part * 16384 + row * 128) + sw;
        soB[c] = soA[c] + 32768u;
    }

    float acc[2][4][4];
    #pragma unroll
    for (int mt = 0; mt < 2; mt++)
        #pragma unroll
        for (int nt = 0; nt < 4; nt++)
            #pragma unroll
            for (int e = 0; e < 4; e++) acc[mt][nt][e] = 0.f;

    uint32_t aoff = sb + (uint32_t)((wm * 32 + (lane & 15)) * 128);
    uint32_t boff = sb + 32768u + (uint32_t)((wn * 32 + (lane & 15)) * 128);
    uint32_t ct[4];
    #pragma unroll
    for (int kh = 0; kh < 4; kh++)
        ct[kh] = (uint32_t)((((2 * kh + (lane >> 4))) ^ (lane & 7)) * 16);

    int nit = K / 64;
    // prologue
    {
        #pragma unroll
        for (int c = 0; c < 4; c++){ cpasync16(sb + soA[c], gA[c]); cpasync16(sb + soB[c], gB[c]); }
        cpcommit();
        if (nit > 1){
            #pragma unroll
            for (int c = 0; c < 4; c++){ cpasync16(sb + 65536u + soA[c], gA[c] + 64); cpasync16(sb + 65536u + soB[c], gB[c] + 64); }
        }
        cpcommit();
    }

    int cur = 0, nxt = 2;
    for (int it = 0; it < nit; it++){
        cpwait1();
        __syncthreads();
        if (it + 2 < nit){
            uint32_t bo = (uint32_t)nxt * 65536u;
            int k0 = (it + 2) * 64;
            #pragma unroll
            for (int c = 0; c < 4; c++){ cpasync16(sb + bo + soA[c], gA[c] + k0); cpasync16(sb + bo + soB[c], gB[c] + k0); }
        }
        cpcommit();

        uint32_t bufo = (uint32_t)cur * 65536u;
        #pragma unroll
        for (int kh = 0; kh < 4; kh++){
            uint32_t ah[2][4], al[2][4], bh[2][4], bl[2][4];
            #pragma unroll
            for (int mt = 0; mt < 2; mt++){
                uint32_t base = aoff + bufo + (uint32_t)(mt * 2048);
                ldsm4(ah[mt], base + ct[kh]);
                ldsm4(al[mt], base + 16384u + ct[kh]);
            }
            #pragma unroll
            for (int g = 0; g < 2; g++){
                uint32_t base = boff + bufo + (uint32_t)(g * 2048);
                ldsm4(bh[g], base + ct[kh]);
                ldsm4(bl[g], base + 16384u + ct[kh]);
            }
            #pragma unroll
            for (int mt = 0; mt < 2; mt++)
                #pragma unroll
                for (int nt = 0; nt < 4; nt++){
                    int g = nt >> 1, s = nt & 1;
                    mma16816(acc[mt][nt], ah[mt], bh[g][s], bh[g][s + 2]);
                    mma16816(acc[mt][nt], ah[mt], bl[g][s], bl[g][s + 2]);
                    mma16816(acc[mt][nt], al[mt], bh[g][s], bh[g][s + 2]);
                }
        }
        if (++cur == 3) cur = 0;
        if (++nxt == 3) nxt = 0;
    }

    // epilogue
    #pragma unroll
    for (int mt = 0; mt < 2; mt++){
        int m = m0 + wm * 32 + mt * 16 + (lane >> 2);
        #pragma unroll
        for (int nt = 0; nt < 4; nt++){
            int col = n0 + wn * 32 + nt * 8 + (lane & 3) * 2;
            if (col < N){
                size_t i0 = (size_t)m * N + col;
                size_t i1 = (size_t)(m + 8) * N + col;
                float2 v0 = make_float2(acc[mt][nt][0], acc[mt][nt][1]);
                float2 v1 = make_float2(acc[mt][nt][2], acc[mt][nt][3]);
                if (R){
                    float2 r0 = *(const float2*)(R + i0);
                    float2 r1 = *(const float2*)(R + i1);
                    v0.x += r0.x; v0.y += r0.y;
                    v1.x += r1.x; v1.y += r1.y;
                }
                *(float2*)(C + i0) = v0;
                *(float2*)(C + i1) = v1;
            }
        }
    }
}

// ---------------- embedding ----------------
__global__ void k_embed(const float* __restrict__ x, const float* __restrict__ W){
    int idx = blockIdx.x * blockDim.x + threadIdx.x;
    if (idx >= NTOK * DMODEL) return;
    int t = idx / DMODEL, d = idx % DMODEL;
    float x0 = x[t*3+0]; if (x0 == -100.f) x0 = 0.f;
    float x1 = x[t*3+1]; if (x1 == -100.f) x1 = 0.f;
    float x2 = x[t*3+2]; if (x2 == -100.f) x2 = 0.f;
    float acc = x0 * W[0*DMODEL + d] + x1 * W[1*DMODEL + d] + x2 * W[2*DMODEL + d];
    if (d < 510){
        int c = d / 170, r = d % 170;
        float xv = (c == 0) ? x0 : ((c == 1) ? x1 : x2);
        float pe;
        if (r < 85) pe = sinf(xv * exp2f((float)r));
        else        pe = cosf(xv * exp2f((float)(r - 85)));
        acc += pe;
    }
    g_h[idx] = acc;
}

// ---------------- rmsnorm ----------------
__global__ void k_rmsnorm(const float* __restrict__ x, const float* __restrict__ w,
                          float* __restrict__ o, __nv_bfloat16* __restrict__ oh,
                          __nv_bfloat16* __restrict__ ol, int D){
    int t = blockIdx.x;
    const float* xr = x + (size_t)t * D;
    float ss = 0.f;
    for (int d = threadIdx.x; d < D; d += blockDim.x){
        float v = xr[d];
        ss += v * v;
    }
    ss = blockReduceSum(ss);
    float rs = rsqrtf(ss / (float)D + 1e-5f);
    for (int d = threadIdx.x; d < D; d += blockDim.x){
        float v = xr[d] * rs * w[d];
        o[(size_t)t * D + d] = v;
        __nv_bfloat16 hi = __float2bfloat16_rn(v);
        oh[(size_t)t * D + d] = hi;
        ol[(size_t)t * D + d] = __float2bfloat16_rn(v - __bfloat162float(hi));
    }
}

// ---------------- conv + silu ----------------
__global__ void k_conv(const float* __restrict__ cw, const float* __restrict__ cb){
    int idx = blockIdx.x * blockDim.x + threadIdx.x;
    if (idx >= NTOK * CONVDIM) return;
    int t = idx / CONVDIM, ch = idx % CONVDIM;
    int l = t % SEQL;
    float acc = cb[ch];
    #pragma unroll
    for (int k = 0; k < DCONV; k++){
        int l2 = l + k - (DCONV - 1);
        if (l2 >= 0)
            acc += g_zx[(size_t)(t + l2 - l) * DINPROJ + DINNER + ch] * cw[ch*DCONV + k];
    }
    g_xc[idx] = siluf(acc);
}

// ---------------- dt prep ----------------
__global__ void k_dt(const float* __restrict__ dtb, const float* __restrict__ Alog){
    int bc = blockIdx.x >> 4;
    int h  = blockIdx.x & 15;
    int i  = threadIdx.x;
    int t  = bc * CHUNKL + i;
    float d = softplusf(g_zx[(size_t)t * DINPROJ + 2176 + h] + dtb[h]);
    float A = -expf(Alog[h]);
    __shared__ float sh[CHUNKL];
    sh[i] = d * A;
    __syncthreads();
    #pragma unroll
    for (int off = 1; off < CHUNKL; off <<= 1){
        float v = (i >= off) ? sh[i - off] : 0.f;
        __syncthreads();
        sh[i] += v;
        __syncthreads();
    }
    g_dtv [t*NH + h] = d;
    g_acum[t*NH + h] = sh[i];
    if (i == CHUNKL - 1) g_dec[blockIdx.x] = expf(sh[i]);
}

// ---------------- scores ----------------
__global__ void k_scores(){
    extern __shared__ float smf[];
    float* Csh = smf;
    float* Bsh = smf + 128*65;
    int bc = blockIdx.x;
    int t0 = bc * CHUNKL;
    int tid = threadIdx.x;
    for (int idx = tid; idx < CHUNKL*DSTATE; idx += 256){
        int j = idx >> 6, n = idx & 63;
        Csh[j*65 + n] = g_xc[(size_t)(t0+j)*CONVDIM + DINNER + DSTATE + n];
        Bsh[j*65 + n] = g_xc[(size_t)(t0+j)*CONVDIM + DINNER + n];
    }
    __syncthreads();
    int i0 = (tid >> 4) * 8;
    int j0 = (tid & 15) * 8;
    float acc[8][8];
    #pragma unroll
    for (int r = 0; r < 8; r++)
        #pragma unroll
        for (int c = 0; c < 8; c++) acc[r][c] = 0.f;
    for (int n = 0; n < DSTATE; n++){
        float a[8], b[8];
        #pragma unroll
        for (int r = 0; r < 8; r++) a[r] = Csh[(i0+r)*65 + n];
        #pragma unroll
        for (int c = 0; c < 8; c++) b[c] = Bsh[(j0+c)*65 + n];
        #pragma unroll
        for (int r = 0; r < 8; r++)
            #pragma unroll
            for (int c = 0; c < 8; c++) acc[r][c] += a[r]*b[c];
    }
    float* out = g_sc + (size_t)bc * CHUNKL * CHUNKL;
    #pragma unroll
    for (int r = 0; r < 8; r++)
        #pragma unroll
        for (int c = 0; c < 8; c++)
            out[(i0+r)*CHUNKL + j0 + c] = acc[r][c];
}

// ---------------- fused y = y_diag + y_off + D*xh, per (b,c,h) --------------
// dynamic smem: xsh[128*64] + hsh[64*64]
__global__ void k_ssd_y(const float* __restrict__ Dp){
    extern __shared__ float smf[];
    float* xsh = smf;             // [128][64]
    float* hsh = smf + CHUNKL*HD; // [64][64] (p-major)
    __shared__ float ash[CHUNKL], dsh[CHUNKL];
    int bc = blockIdx.x >> 4, h = blockIdx.x & 15;
    int i  = threadIdx.x;
    int t0 = bc * CHUNKL;
    ash[i] = g_acum[(t0+i)*NH + h];
    dsh[i] = g_dtv [(t0+i)*NH + h];
    for (int idx = i; idx < CHUNKL*HD; idx += CHUNKL)
        xsh[idx] = g_xc[(size_t)(t0 + (idx >> 6))*CONVDIM + h*HD + (idx & 63)];
    const float* hbase = g_hs + (size_t)blockIdx.x * (HD*DSTATE);
    for (int idx = i; idx < HD*DSTATE; idx += CHUNKL) hsh[idx] = hbase[idx];
    __syncthreads();

    float ai = ash[i];
    float Dh = Dp[h];
    // init acc with D * x
    float acc[HD];
    #pragma unroll
    for (int p = 0; p < HD; p++) acc[p] = Dh * xsh[i*HD + p];

    // --- diag part with exp-window ---
    // smallest j in [0,i] with ash[j] < ai + AWIN (ash strictly decreasing)
    int lo = 0, hi = i;
    while (lo < hi){
        int mid = (lo + hi) >> 1;
        if (ash[mid] < ai + AWIN) hi = mid; else lo = mid + 1;
    }
    const float* srow = g_sc + (size_t)bc * CHUNKL * CHUNKL + (size_t)i * CHUNKL;
    for (int j = lo; j <= i; j++){
        float m = srow[j] * expf(ai - ash[j]) * dsh[j];
        const float* xr = &xsh[j*HD];
        #pragma unroll
        for (int p = 0; p < HD; p++) acc[p] += m * xr[p];
    }

    // --- off-diagonal part: ei * C_i . hs[p][:] ---
    if (ai > -AWIN){
        float ei = expf(ai);
        const float* crow = g_xc + (size_t)(t0+i)*CONVDIM + DINNER + DSTATE;
        #pragma unroll
        for (int h2 = 0; h2 < 2; h2++){
            float creg[32];
            #pragma unroll
            for (int n = 0; n < 32; n++) creg[n] = ei * crow[h2*32 + n];
            #pragma unroll 8
            for (int p = 0; p < HD; p++){
                const float4* hr = (const float4*)&hsh[p*DSTATE + h2*32];
                float a = 0.f;
                #pragma unroll
                for (int q = 0; q < 8; q++){
                    float4 v = hr[q];
                    a += creg[q*4+0]*v.x + creg[q*4+1]*v.y + creg[q*4+2]*v.z + creg[q*4+3]*v.w;
                }
                acc[p] += a;
            }
        }
    }

    float* yrow = g_y + (size_t)(t0+i)*DINNER + h*HD;
    #pragma unroll
    for (int p = 0; p < HD; p++) yrow[p] = acc[p];
}

// ---------------- chunk states (with exp-window) ----------------
__global__ void k_state(){
    extern __shared__ float smf[];
    float* xsh = smf;
    float* bsh = smf + CHUNKL*HD;
    __shared__ float wsh[CHUNKL];
    __shared__ float ash_s[CHUNKL];
    int bc = blockIdx.x >> 4, h = blockIdx.x & 15;
    int t0 = bc * CHUNKL;
    int tid = threadIdx.x;
    for (int idx = tid; idx < CHUNKL*HD; idx += 256){
        int j = idx >> 6, q = idx & 63;
        xsh[idx] = g_xc[(size_t)(t0+j)*CONVDIM + h*HD + q];
        bsh[idx] = g_xc[(size_t)(t0+j)*CONVDIM + DINNER + q];
    }
    if (tid < CHUNKL) ash_s[tid] = g_acum[(t0 + tid)*NH + h];
    __syncthreads();
    if (tid < CHUNKL){
        float alast = ash_s[CHUNKL - 1];
        wsh[tid] = expf(alast - ash_s[tid]) * g_dtv[(t0 + tid)*NH + h];
    }
    __syncthreads();
    float alast = ash_s[CHUNKL - 1];
    int lo = 0, hi = CHUNKL - 1;
    while (lo < hi){
        int mid = (lo + hi) >> 1;
        if (ash_s[mid] < alast + AWIN) hi = mid; else lo = mid + 1;
    }
    int p  = tid & 63;
    int n0 = (tid >> 6) << 4;
    float acc[16];
    #pragma unroll
    for (int k = 0; k < 16; k++) acc[k] = 0.f;
    for (int j = lo; j < CHUNKL; j++){
        float xw = xsh[j*HD + p] * wsh[j];
        const float* br = &bsh[j*HD + n0];
        #pragma unroll
        for (int k = 0; k < 16; k++) acc[k] += xw * br[k];
    }
    float* so = g_S + (size_t)blockIdx.x * (HD*DSTATE);
    #pragma unroll
    for (int k = 0; k < 16; k++) so[p*DSTATE + n0 + k] = acc[k];
}

// ---------------- scan ----------------
__global__ void k_scan(){
    int b = blockIdx.x >> 4, h = blockIdx.x & 15;
    int tid = threadIdx.x;
    float st[16];
    #pragma unroll
    for (int k = 0; k < 16; k++) st[k] = 0.f;
    for (int c = 0; c < NCH; c++){
        int bch = (b*NCH + c)*NH + h;
        size_t base = (size_t)bch * (HD*DSTATE);
        float dc = g_dec[bch];
        #pragma unroll
        for (int k = 0; k < 16; k++){
            int idx = k*256 + tid;
            g_hs[base + idx] = st[k];
            st[k] = st[k]*dc + g_S[base + idx];
        }
    }
}

// ---------------- gate ----------------
__global__ void k_gate(const float* __restrict__ gw){
    int t = blockIdx.x;
    int tid = threadIdx.x;
    float v[4]; float ss = 0.f;
    #pragma unroll
    for (int k = 0; k < 4; k++){
        int d = k*256 + tid;
        float z = g_zx[(size_t)t*DINPROJ + d];
        float vv = g_y[(size_t)t*DINNER + d] * siluf(z);
        v[k] = vv; ss += vv*vv;
    }
    ss = blockReduceSum(ss);
    float rs = rsqrtf(ss / (float)DINNER + 1e-5f);
    #pragma unroll
    for (int k = 0; k < 4; k++){
        int d = k*256 + tid;
        float o = v[k] * rs * gw[d];
        __nv_bfloat16 hi = __float2bfloat16_rn(o);
        g_ygh[(size_t)t*DINNER + d] = hi;
        g_ygl[(size_t)t*DINNER + d] = __float2bfloat16_rn(o - __bfloat162float(hi));
    }
}

// ---------------- head ----------------
__global__ void k_head(const float* __restrict__ hw, const float* __restrict__ hb,
                       float* __restrict__ out){
    int idx = blockIdx.x * blockDim.x + threadIdx.x;
    if (idx >= NTOK * KOUT) return;
    int t = idx / KOUT, n = idx % KOUT;
    float acc = hb[n];
    const float* xr = g_xn + (size_t)t * DMODEL;
    for (int k = 0; k < DMODEL; k++) acc += xr[k] * hw[k*KOUT + n];
    out[idx] = acc;
}

// ---------------- host ----------------
extern "C" void kernel_launch(void* const* d_in, const int* in_sizes, int n_in,
                              void* d_out, int out_size){
    const float* x      = (const float*)d_in[0];
    const float* Wembed = (const float*)d_in[1];
    const float* rmsw   = (const float*)d_in[2];
    const float* inw    = (const float*)d_in[3];
    const float* convw  = (const float*)d_in[4];
    const float* convb  = (const float*)d_in[5];
    const float* dtb    = (const float*)d_in[6];
    const float* alog   = (const float*)d_in[7];
    const float* dparam = (const float*)d_in[8];
    const float* gnw    = (const float*)d_in[9];
    const float* outw   = (const float*)d_in[10];
    const float* fnw    = (const float*)d_in[11];
    const float* hw     = (const float*)d_in[12];
    const float* hb     = (const float*)d_in[13];
    float* out = (float*)d_out;

    float *p_h, *p_xn, *p_zx;
    cudaGetSymbolAddress((void**)&p_h,  g_h);
    cudaGetSymbolAddress((void**)&p_xn, g_xn);
    cudaGetSymbolAddress((void**)&p_zx, g_zx);
    __nv_bfloat16 *p_xnh, *p_xnl, *p_ygh, *p_ygl;
    cudaGetSymbolAddress((void**)&p_xnh, g_xnh);
    cudaGetSymbolAddress((void**)&p_xnl, g_xnl);
    cudaGetSymbolAddress((void**)&p_ygh, g_ygh);
    cudaGetSymbolAddress((void**)&p_ygl, g_ygl);
    __nv_bfloat16 *p_wih, *p_wil, *p_woh, *p_wol;
    cudaGetSymbolAddress((void**)&p_wih, g_wih);
    cudaGetSymbolAddress((void**)&p_wil, g_wil);
    cudaGetSymbolAddress((void**)&p_woh, g_woh);
    cudaGetSymbolAddress((void**)&p_wol, g_wol);

    const int SCORES_SMEM = 2*128*65*4;
    const int STATE_SMEM  = 2*CHUNKL*HD*4;
    const int SSDY_SMEM   = (CHUNKL*HD + HD*DSTATE)*4;  // 49152
    const int TG_SMEM     = 3*65536;                    // 196608
    cudaFuncSetAttribute(k_scores, cudaFuncAttributeMaxDynamicSharedMemorySize, SCORES_SMEM);
    cudaFuncSetAttribute(k_state,  cudaFuncAttributeMaxDynamicSharedMemorySize, STATE_SMEM);
    cudaFuncSetAttribute(k_ssd_y,  cudaFuncAttributeMaxDynamicSharedMemorySize, SSDY_SMEM);
    cudaFuncSetAttribute(k_tgemm,  cudaFuncAttributeMaxDynamicSharedMemorySize, TG_SMEM);

    k_prep<<<dim3(DMODEL/32, NPAD_IN/32, NLAYERS), dim3(32,8)>>>(
        inw, p_wih, p_wil, DMODEL, DINPROJ, NPAD_IN);
    k_prep<<<dim3(DINNER/32, DMODEL/32, NLAYERS), dim3(32,8)>>>(
        outw, p_woh, p_wol, DINNER, DMODEL, DMODEL);

    k_embed<<<(NTOK*DMODEL + 255)/256, 256>>>(x, Wembed);

    for (int l = 0; l < NLAYERS; l++){
        k_rmsnorm<<<NTOK, 256>>>(p_h, rmsw + (size_t)l*DMODEL, p_xn, p_xnh, p_xnl, DMODEL);
        k_tgemm<<<dim3(NPAD_IN/128, NTOK/128), 512, TG_SMEM>>>(
            p_xnh, p_xnl,
            p_wih + (size_t)l*NPAD_IN*DMODEL, p_wil + (size_t)l*NPAD_IN*DMODEL,
            p_zx, nullptr, NTOK, DINPROJ, DMODEL);
        k_conv<<<(NTOK*CONVDIM + 255)/256, 256>>>(convw + (size_t)l*CONVDIM*DCONV,
                                                  convb + (size_t)l*CONVDIM);
        k_dt<<<NBC*NH, CHUNKL>>>(dtb + (size_t)l*NH, alog + (size_t)l*NH);
        k_scores<<<NBC, 256, SCORES_SMEM>>>();
        k_state<<<NBC*NH, 256, STATE_SMEM>>>();
        k_scan<<<BSZ*NH, 256>>>();
        k_ssd_y<<<NBC*NH, CHUNKL, SSDY_SMEM>>>(dparam + (size_t)l*NH);
        k_gate<<<NTOK, 256>>>(gnw + (size_t)l*DINNER);
        k_tgemm<<<dim3(DMODEL/128, NTOK/128), 512, TG_SMEM>>>(
            p_ygh, p_ygl,
            p_woh + (size_t)l*DMODEL*DINNER, p_wol + (size_t)l*DMODEL*DINNER,
            p_h, p_h, NTOK, DMODEL, DINNER);
    }

    k_rmsnorm<<<NTOK, 256>>>(p_h, fnw, p_xn, p_xnh, p_xnl, DMODEL);
    k_head<<<(NTOK*KOUT + 255)/256, 256>>>(hw, hb, out);
}